// round 3
// baseline (speedup 1.0000x reference)
#include <cuda_runtime.h>
#include <cuda_bf16.h>
#include <cstdint>

#define TV 8192
#define BHV 32
#define LN_EPS 1e-5f
#define DEN_EPS 1e-6f

// Scratch (allocation-free: __device__ globals)
__device__ uint32_t g_kp[(size_t)BHV * TV * 32];     // 32 MB: kp as 2xbf16 per word [bh][t][m/2]
__device__ float    g_part[(size_t)BHV * 64 * 4096]; // 32 MB: partial kv per (bh,tile)
__device__ float    g_kv[(size_t)BHV * 4096];        // kv[bh][m][n] (x0.1)

// ---------------- helpers ----------------
__device__ __forceinline__ float wredsum(float v) {
    v += __shfl_xor_sync(0xffffffffu, v, 16);
    v += __shfl_xor_sync(0xffffffffu, v, 8);
    v += __shfl_xor_sync(0xffffffffu, v, 4);
    v += __shfl_xor_sync(0xffffffffu, v, 2);
    v += __shfl_xor_sync(0xffffffffu, v, 1);
    return v;
}
__device__ __forceinline__ float featexp(float x) {
    return __expf(fminf(fmaxf(x, -15.f), 15.f)) * 0.1f;
}
__device__ __forceinline__ uint32_t prmt_(uint32_t a, uint32_t b, uint32_t s) {
    uint32_t d;
    asm("prmt.b32 %0,%1,%2,%3;" : "=r"(d) : "r"(a), "r"(b), "r"(s));
    return d;
}
// pack one float as (bf16_hi | bf16_lo<<16), hi+lo ~ 16-17 mantissa bits
__device__ __forceinline__ uint32_t packhl(float x) {
    __nv_bfloat16 h = __float2bfloat16_rn(x);
    float hf = __bfloat162float(h);
    __nv_bfloat16 l = __float2bfloat16_rn(x - hf);
    return (uint32_t)__bfloat16_as_ushort(h) | ((uint32_t)__bfloat16_as_ushort(l) << 16);
}
// pack two floats as two single bf16 (low = x, high = y)
__device__ __forceinline__ uint32_t pack2(float x, float y) {
    __nv_bfloat162 b = __floats2bfloat162_rn(x, y);
    return *(uint32_t*)&b;
}
__device__ __forceinline__ float2 unpk2(uint32_t p) {
    __nv_bfloat162 b = *(__nv_bfloat162*)&p;
    return make_float2(__bfloat162float(b.x), __bfloat162float(b.y));
}

__device__ __forceinline__ void mma_bf16(float* c, uint32_t a0, uint32_t a1, uint32_t a2, uint32_t a3,
                                         uint32_t b0, uint32_t b1) {
    asm("mma.sync.aligned.m16n8k16.row.col.f32.bf16.bf16.f32 "
        "{%0,%1,%2,%3},{%4,%5,%6,%7},{%8,%9},{%0,%1,%2,%3};"
        : "+f"(c[0]), "+f"(c[1]), "+f"(c[2]), "+f"(c[3])
        : "r"(a0), "r"(a1), "r"(a2), "r"(a3), "r"(b0), "r"(b1));
}

struct Afrag { uint32_t h[4], l[4]; };
struct Bfrag { uint32_t h[2], l[2]; };

// A row-major [row][k] (packed hi/lo words), rows r,r+8, k pairs (kb,kb+1),(kb+8,kb+9)
__device__ __forceinline__ Afrag lda(const uint32_t* base, int stride, int r, int kb) {
    uint2 p0 = *(const uint2*)(base + r * stride + kb);
    uint2 p1 = *(const uint2*)(base + (r + 8) * stride + kb);
    uint2 p2 = *(const uint2*)(base + r * stride + kb + 8);
    uint2 p3 = *(const uint2*)(base + (r + 8) * stride + kb + 8);
    Afrag f;
    f.h[0] = prmt_(p0.x, p0.y, 0x5410); f.l[0] = prmt_(p0.x, p0.y, 0x7632);
    f.h[1] = prmt_(p1.x, p1.y, 0x5410); f.l[1] = prmt_(p1.x, p1.y, 0x7632);
    f.h[2] = prmt_(p2.x, p2.y, 0x5410); f.l[2] = prmt_(p2.x, p2.y, 0x7632);
    f.h[3] = prmt_(p3.x, p3.y, 0x5410); f.l[3] = prmt_(p3.x, p3.y, 0x7632);
    return f;
}
// B col-major: stored as [n][k] (k contiguous)
__device__ __forceinline__ Bfrag ldb(const uint32_t* base, int stride, int n, int kb) {
    uint2 q0 = *(const uint2*)(base + n * stride + kb);
    uint2 q1 = *(const uint2*)(base + n * stride + kb + 8);
    Bfrag f;
    f.h[0] = prmt_(q0.x, q0.y, 0x5410); f.l[0] = prmt_(q0.x, q0.y, 0x7632);
    f.h[1] = prmt_(q1.x, q1.y, 0x5410); f.l[1] = prmt_(q1.x, q1.y, 0x7632);
    return f;
}
__device__ __forceinline__ void mma3(float* c, const Afrag& A, const Bfrag& B) {
    mma_bf16(c, A.h[0], A.h[1], A.h[2], A.h[3], B.h[0], B.h[1]);
    mma_bf16(c, A.h[0], A.h[1], A.h[2], A.h[3], B.l[0], B.l[1]);
    mma_bf16(c, A.l[0], A.l[1], A.l[2], A.l[3], B.h[0], B.h[1]);
}

// smem word offsets, pass1: KN[128][72], PJ[64][72], VT[64][136], KT[64][136]
#define P1_KN 0
#define P1_PJ 9216
#define P1_VT 13824
#define P1_KT 22528
#define P1_BYTES ((22528 + 8704) * 4)

// pass2: QN[128][72], PJ[64][72], KVT[64][72], QP[128][72], STG[128][68]f32, DEN[128]f32
#define P2_QN 0
#define P2_PJ 9216
#define P2_KVT 13824
#define P2_QP 18432
#define P2_STG 27648
#define P2_DEN (27648 + 8704)
#define P2_BYTES ((27648 + 8704 + 128) * 4)

// ---------------------------------------------------------------------------
// Pass 1: CTA = (tile of 128 tokens, bh). LN+L2(k)->KN, LN(v)->VT,
//   GEMM1: kp = featexp(KN @ PJ^T) -> g_kp + KT;  GEMM2: part = KT @ VT^T.
// ---------------------------------------------------------------------------
extern "C" __global__ void __launch_bounds__(256) fa_pass1(
    const float* __restrict__ k, const float* __restrict__ v,
    const float* __restrict__ proj, const float* __restrict__ gamma,
    const float* __restrict__ beta)
{
    extern __shared__ uint32_t sm[];
    uint32_t* KN = sm + P1_KN;
    uint32_t* PJ = sm + P1_PJ;
    uint32_t* VT = sm + P1_VT;
    uint32_t* KT = sm + P1_KT;

    const int tid = threadIdx.x, lane = tid & 31, wid = tid >> 5;
    const int bh = blockIdx.y, tile = blockIdx.x, t0 = tile * 128;

    // PJ[m][n] = proj[n][m] (B col-major for GEMM1)
    for (int i = tid; i < 4096; i += 256) {
        int n = i >> 6, m = i & 63;
        PJ[m * 72 + n] = packhl(proj[i]);
    }

    const float g0 = gamma[lane], g1 = gamma[lane + 32];
    const float be0 = beta[lane], be1 = beta[lane + 32];

    // LN + L2 of k -> KN[t][k]
    {
        const float* kr = k + ((size_t)bh * TV + t0 + wid * 16) * 64;
        float a[16], b[16];
#pragma unroll
        for (int i = 0; i < 16; i++) { a[i] = kr[i * 64 + lane]; b[i] = kr[i * 64 + lane + 32]; }
#pragma unroll
        for (int i = 0; i < 16; i++) {
            float x0 = a[i], x1 = b[i];
            float s = wredsum(x0 + x1), ss = wredsum(x0 * x0 + x1 * x1);
            float mu = s * (1.f / 64.f);
            float rstd = rsqrtf(ss * (1.f / 64.f) - mu * mu + LN_EPS);
            float y0 = (x0 - mu) * rstd * g0 + be0;
            float y1 = (x1 - mu) * rstd * g1 + be1;
            float n2 = wredsum(y0 * y0 + y1 * y1);
            float inv = 1.f / fmaxf(sqrtf(n2), 1e-12f);
            int t = wid * 16 + i;
            KN[t * 72 + lane] = packhl(y0 * inv);
            KN[t * 72 + lane + 32] = packhl(y1 * inv);
        }
    }
    // LN of v -> VT[n][t] (transposed, B of GEMM2)
    {
        const float* vr = v + ((size_t)bh * TV + t0 + wid * 16) * 64;
        float a[16], b[16];
#pragma unroll
        for (int i = 0; i < 16; i++) { a[i] = vr[i * 64 + lane]; b[i] = vr[i * 64 + lane + 32]; }
#pragma unroll
        for (int i = 0; i < 16; i++) {
            float x0 = a[i], x1 = b[i];
            float s = wredsum(x0 + x1), ss = wredsum(x0 * x0 + x1 * x1);
            float mu = s * (1.f / 64.f);
            float rstd = rsqrtf(ss * (1.f / 64.f) - mu * mu + LN_EPS);
            int t = wid * 16 + i;
            VT[lane * 136 + t] = packhl((x0 - mu) * rstd * g0 + be0);
            VT[(lane + 32) * 136 + t] = packhl((x1 - mu) * rstd * g1 + be1);
        }
    }
    __syncthreads();

    const int r = lane >> 2, qk = (lane & 3) * 2;

    // GEMM1: D1[t][m] = KN[t][:] . PJ[m][:]   (128x64x64)
    float acc[8][4];
#pragma unroll
    for (int f = 0; f < 8; f++)
#pragma unroll
        for (int j = 0; j < 4; j++) acc[f][j] = 0.f;
#pragma unroll
    for (int ks = 0; ks < 4; ks++) {
        Afrag A = lda(KN, 72, wid * 16 + r, ks * 16 + qk);
#pragma unroll
        for (int f = 0; f < 8; f++) {
            Bfrag B = ldb(PJ, 72, f * 8 + r, ks * 16 + qk);
            mma3(acc[f], A, B);
        }
    }

    // Epilogue1: kp = featexp(D1) -> g_kp (2xbf16) and KT[m][t] (hi/lo)
    {
        uint32_t* gkp = g_kp + ((size_t)bh * TV + t0) * 32;
        const int tr = wid * 16 + r;
#pragma unroll
        for (int f = 0; f < 8; f++) {
            float x0 = featexp(acc[f][0]), x1 = featexp(acc[f][1]);
            float x2 = featexp(acc[f][2]), x3 = featexp(acc[f][3]);
            int c = f * 8 + qk;
            gkp[tr * 32 + (c >> 1)] = pack2(x0, x1);
            gkp[(tr + 8) * 32 + (c >> 1)] = pack2(x2, x3);
            KT[c * 136 + tr] = packhl(x0);
            KT[(c + 1) * 136 + tr] = packhl(x1);
            KT[c * 136 + tr + 8] = packhl(x2);
            KT[(c + 1) * 136 + tr + 8] = packhl(x3);
        }
    }
    __syncthreads();

    // GEMM2: D2[m][n] = sum_t KT[m][t] * VT[n][t]  (64x64x128)
    const int mb = wid & 3, nh = wid >> 2;
    float acc2[4][4];
#pragma unroll
    for (int f = 0; f < 4; f++)
#pragma unroll
        for (int j = 0; j < 4; j++) acc2[f][j] = 0.f;
#pragma unroll
    for (int ks = 0; ks < 8; ks++) {
        Afrag A = lda(KT, 136, mb * 16 + r, ks * 16 + qk);
#pragma unroll
        for (int f = 0; f < 4; f++) {
            Bfrag B = ldb(VT, 136, nh * 32 + f * 8 + r, ks * 16 + qk);
            mma3(acc2[f], A, B);
        }
    }
    float* gp = g_part + (size_t)(bh * 64 + tile) * 4096;
#pragma unroll
    for (int f = 0; f < 4; f++) {
        int m = mb * 16 + r, n = nh * 32 + f * 8 + qk;
        *(float2*)(gp + m * 64 + n) = make_float2(acc2[f][0], acc2[f][1]);
        *(float2*)(gp + (m + 8) * 64 + n) = make_float2(acc2[f][2], acc2[f][3]);
    }
}

// ---------------------------------------------------------------------------
extern "C" __global__ void __launch_bounds__(256) fa_reduce()
{
    const int idx = blockIdx.x * 256 + threadIdx.x;  // 0 .. 131071
    const int bh = idx >> 12, e = idx & 4095;
    const float* p = g_part + (size_t)bh * 64 * 4096 + e;
    float s = 0.f;
#pragma unroll
    for (int c = 0; c < 64; ++c) s += p[(size_t)c * 4096];
    g_kv[idx] = s * 0.1f;
}

// ---------------------------------------------------------------------------
// Pass 2: LN+L2(q)->QN, GEMM3 qp=featexp(QN@PJ^T), denom=qp.kp,
//   GEMM4 qkv = 0.1*qp@kv, /denom, final LN -> out
// ---------------------------------------------------------------------------
extern "C" __global__ void __launch_bounds__(256) fa_pass2(
    const float* __restrict__ q, const float* __restrict__ proj,
    const float* __restrict__ gamma, const float* __restrict__ beta,
    float* __restrict__ out)
{
    extern __shared__ uint32_t sm[];
    uint32_t* QN = sm + P2_QN;
    uint32_t* PJ = sm + P2_PJ;
    uint32_t* KVT = sm + P2_KVT;
    uint32_t* QP = sm + P2_QP;
    float* STG = (float*)(sm + P2_STG);
    float* DEN = (float*)(sm + P2_DEN);

    const int tid = threadIdx.x, lane = tid & 31, wid = tid >> 5;
    const int bh = blockIdx.y, tile = blockIdx.x, t0 = tile * 128;

    for (int i = tid; i < 4096; i += 256) {
        int n = i >> 6, m = i & 63;
        PJ[m * 72 + n] = packhl(proj[i]);
    }
    {
        const float* kvg = g_kv + (size_t)bh * 4096;
        for (int i = tid; i < 4096; i += 256) {
            int m = i >> 6, n = i & 63;
            KVT[n * 72 + m] = packhl(kvg[i]);
        }
    }

    const float g0 = gamma[lane], g1 = gamma[lane + 32];
    const float be0 = beta[lane], be1 = beta[lane + 32];

    // LN + L2 of q
    {
        const float* qr = q + ((size_t)bh * TV + t0 + wid * 16) * 64;
        float a[16], b[16];
#pragma unroll
        for (int i = 0; i < 16; i++) { a[i] = qr[i * 64 + lane]; b[i] = qr[i * 64 + lane + 32]; }
#pragma unroll
        for (int i = 0; i < 16; i++) {
            float x0 = a[i], x1 = b[i];
            float s = wredsum(x0 + x1), ss = wredsum(x0 * x0 + x1 * x1);
            float mu = s * (1.f / 64.f);
            float rstd = rsqrtf(ss * (1.f / 64.f) - mu * mu + LN_EPS);
            float y0 = (x0 - mu) * rstd * g0 + be0;
            float y1 = (x1 - mu) * rstd * g1 + be1;
            float n2 = wredsum(y0 * y0 + y1 * y1);
            float inv = 1.f / fmaxf(sqrtf(n2), 1e-12f);
            int t = wid * 16 + i;
            QN[t * 72 + lane] = packhl(y0 * inv);
            QN[t * 72 + lane + 32] = packhl(y1 * inv);
        }
    }
    __syncthreads();

    const int r = lane >> 2, qk = (lane & 3) * 2;
    const int tr = wid * 16 + r;

    // GEMM3: D3[t][m] = QN @ PJ^T
    float acc[8][4];
#pragma unroll
    for (int f = 0; f < 8; f++)
#pragma unroll
        for (int j = 0; j < 4; j++) acc[f][j] = 0.f;
#pragma unroll
    for (int ks = 0; ks < 4; ks++) {
        Afrag A = lda(QN, 72, tr, ks * 16 + qk);
#pragma unroll
        for (int f = 0; f < 8; f++) {
            Bfrag B = ldb(PJ, 72, f * 8 + r, ks * 16 + qk);
            mma3(acc[f], A, B);
        }
    }

    // Epilogue3: qp = featexp(D3) -> QP; denom = sum_m qp*kp (quad reduce)
    {
        const uint32_t* gkp = g_kp + ((size_t)bh * TV + t0) * 32;
        float den0 = 0.f, den1 = 0.f;
#pragma unroll
        for (int f = 0; f < 8; f++) {
            float x0 = featexp(acc[f][0]), x1 = featexp(acc[f][1]);
            float x2 = featexp(acc[f][2]), x3 = featexp(acc[f][3]);
            int c = f * 8 + qk;
            QP[tr * 72 + c] = packhl(x0);
            QP[tr * 72 + c + 1] = packhl(x1);
            QP[(tr + 8) * 72 + c] = packhl(x2);
            QP[(tr + 8) * 72 + c + 1] = packhl(x3);
            float2 k0 = unpk2(gkp[tr * 32 + (c >> 1)]);
            float2 k1 = unpk2(gkp[(tr + 8) * 32 + (c >> 1)]);
            den0 += x0 * k0.x + x1 * k0.y;
            den1 += x2 * k1.x + x3 * k1.y;
        }
        den0 += __shfl_xor_sync(0xffffffffu, den0, 1);
        den0 += __shfl_xor_sync(0xffffffffu, den0, 2);
        den1 += __shfl_xor_sync(0xffffffffu, den1, 1);
        den1 += __shfl_xor_sync(0xffffffffu, den1, 2);
        if ((lane & 3) == 0) { DEN[tr] = den0; DEN[tr + 8] = den1; }
    }
    __syncthreads();

    // GEMM4: D4[t][n] = QP @ KVT^T  (128x64x64)
    float acc2[8][4];
#pragma unroll
    for (int f = 0; f < 8; f++)
#pragma unroll
        for (int j = 0; j < 4; j++) acc2[f][j] = 0.f;
#pragma unroll
    for (int ks = 0; ks < 4; ks++) {
        Afrag A = lda(QP, 72, tr, ks * 16 + qk);
#pragma unroll
        for (int f = 0; f < 8; f++) {
            Bfrag B = ldb(KVT, 72, f * 8 + r, ks * 16 + qk);
            mma3(acc2[f], A, B);
        }
    }

    // Epilogue4: x = 0.1*D4/den -> STG
    {
        float s0 = 0.1f / fmaxf(DEN[tr], DEN_EPS);
        float s1 = 0.1f / fmaxf(DEN[tr + 8], DEN_EPS);
#pragma unroll
        for (int f = 0; f < 8; f++) {
            int c = f * 8 + qk;
            *(float2*)(STG + tr * 68 + c) = make_float2(acc2[f][0] * s0, acc2[f][1] * s0);
            *(float2*)(STG + (tr + 8) * 68 + c) = make_float2(acc2[f][2] * s1, acc2[f][3] * s1);
        }
    }
    __syncthreads();

    // Final LN per token -> out (coalesced)
    float* ob = out + ((size_t)bh * TV + t0 + wid * 16) * 64;
#pragma unroll
    for (int i = 0; i < 16; i++) {
        int t = wid * 16 + i;
        float x0 = STG[t * 68 + lane], x1 = STG[t * 68 + lane + 32];
        float s = wredsum(x0 + x1), ss = wredsum(x0 * x0 + x1 * x1);
        float mu = s * (1.f / 64.f);
        float rstd = rsqrtf(ss * (1.f / 64.f) - mu * mu + LN_EPS);
        ob[i * 64 + lane] = (x0 - mu) * rstd * g0 + be0;
        ob[i * 64 + lane + 32] = (x1 - mu) * rstd * g1 + be1;
    }
}

// ---------------------------------------------------------------------------
extern "C" void kernel_launch(void* const* d_in, const int* in_sizes, int n_in,
                              void* d_out, int out_size)
{
    const float* q     = (const float*)d_in[0];
    const float* k     = (const float*)d_in[1];
    const float* v     = (const float*)d_in[2];
    const float* proj  = (const float*)d_in[3];
    const float* gamma = (const float*)d_in[4];
    const float* beta  = (const float*)d_in[5];
    float* out = (float*)d_out;

    cudaFuncSetAttribute(fa_pass1, cudaFuncAttributeMaxDynamicSharedMemorySize, P1_BYTES);
    cudaFuncSetAttribute(fa_pass2, cudaFuncAttributeMaxDynamicSharedMemorySize, P2_BYTES);

    fa_pass1<<<dim3(64, BHV), 256, P1_BYTES>>>(k, v, proj, gamma, beta);
    fa_reduce<<<512, 256>>>();
    fa_pass2<<<dim3(64, BHV), 256, P2_BYTES>>>(q, proj, gamma, beta, out);
}

// round 4
// speedup vs baseline: 1.6064x; 1.6064x over previous
#include <cuda_runtime.h>
#include <cuda_bf16.h>
#include <cstdint>

#define TV 8192
#define BHV 32
#define LN_EPS 1e-5f
#define DEN_EPS 1e-6f
#define W 72   // smem row stride in words

// Scratch (allocation-free: __device__ globals)
__device__ uint32_t g_kp[(size_t)BHV * TV * 32];      // 32 MB: kp as 2xbf16 [bh][t][m/2]
__device__ float    g_part[(size_t)BHV * 128 * 4096]; // 64 MB: partial kv per (bh,tile64)
__device__ float    g_kv[(size_t)BHV * 4096];         // kv[bh][m][n] (x0.1)

// ---------------- helpers ----------------
__device__ __forceinline__ float featexp(float x) {
    return __expf(fminf(fmaxf(x, -15.f), 15.f)) * 0.1f;
}
__device__ __forceinline__ uint32_t prmt_(uint32_t a, uint32_t b, uint32_t s) {
    uint32_t d;
    asm("prmt.b32 %0,%1,%2,%3;" : "=r"(d) : "r"(a), "r"(b), "r"(s));
    return d;
}
// pack one float as (bf16_hi | bf16_lo<<16)
__device__ __forceinline__ uint32_t packhl(float x) {
    __nv_bfloat16 h = __float2bfloat16_rn(x);
    float hf = __bfloat162float(h);
    __nv_bfloat16 l = __float2bfloat16_rn(x - hf);
    return (uint32_t)__bfloat16_as_ushort(h) | ((uint32_t)__bfloat16_as_ushort(l) << 16);
}
__device__ __forceinline__ uint32_t pack2(float x, float y) {
    __nv_bfloat162 b = __floats2bfloat162_rn(x, y);
    return *(uint32_t*)&b;
}
__device__ __forceinline__ float2 unpk2(uint32_t p) {
    __nv_bfloat162 b = *(__nv_bfloat162*)&p;
    return make_float2(__bfloat162float(b.x), __bfloat162float(b.y));
}
__device__ __forceinline__ float qred(float v) {   // reduce over 4-lane quad
    v += __shfl_xor_sync(0xffffffffu, v, 1);
    v += __shfl_xor_sync(0xffffffffu, v, 2);
    return v;
}

__device__ __forceinline__ void mma_bf16(float* c, uint32_t a0, uint32_t a1, uint32_t a2, uint32_t a3,
                                         uint32_t b0, uint32_t b1) {
    asm("mma.sync.aligned.m16n8k16.row.col.f32.bf16.bf16.f32 "
        "{%0,%1,%2,%3},{%4,%5,%6,%7},{%8,%9},{%0,%1,%2,%3};"
        : "+f"(c[0]), "+f"(c[1]), "+f"(c[2]), "+f"(c[3])
        : "r"(a0), "r"(a1), "r"(a2), "r"(a3), "r"(b0), "r"(b1));
}
struct Afrag { uint32_t h[4], l[4]; };
struct Bfrag { uint32_t h[2], l[2]; };
__device__ __forceinline__ Afrag lda(const uint32_t* base, int r, int kb) {
    uint2 p0 = *(const uint2*)(base + r * W + kb);
    uint2 p1 = *(const uint2*)(base + (r + 8) * W + kb);
    uint2 p2 = *(const uint2*)(base + r * W + kb + 8);
    uint2 p3 = *(const uint2*)(base + (r + 8) * W + kb + 8);
    Afrag f;
    f.h[0] = prmt_(p0.x, p0.y, 0x5410); f.l[0] = prmt_(p0.x, p0.y, 0x7632);
    f.h[1] = prmt_(p1.x, p1.y, 0x5410); f.l[1] = prmt_(p1.x, p1.y, 0x7632);
    f.h[2] = prmt_(p2.x, p2.y, 0x5410); f.l[2] = prmt_(p2.x, p2.y, 0x7632);
    f.h[3] = prmt_(p3.x, p3.y, 0x5410); f.l[3] = prmt_(p3.x, p3.y, 0x7632);
    return f;
}
__device__ __forceinline__ Bfrag ldb(const uint32_t* base, int n, int kb) {
    uint2 q0 = *(const uint2*)(base + n * W + kb);
    uint2 q1 = *(const uint2*)(base + n * W + kb + 8);
    Bfrag f;
    f.h[0] = prmt_(q0.x, q0.y, 0x5410); f.l[0] = prmt_(q0.x, q0.y, 0x7632);
    f.h[1] = prmt_(q1.x, q1.y, 0x5410); f.l[1] = prmt_(q1.x, q1.y, 0x7632);
    return f;
}
__device__ __forceinline__ void mma3(float* c, const Afrag& A, const Bfrag& B) {
    mma_bf16(c, A.h[0], A.h[1], A.h[2], A.h[3], B.h[0], B.h[1]);
    mma_bf16(c, A.h[0], A.h[1], A.h[2], A.h[3], B.l[0], B.l[1]);
    mma_bf16(c, A.l[0], A.l[1], A.l[2], A.l[3], B.h[0], B.h[1]);
}

// LN over 16 register values (quad-cooperative); returns y in place
__device__ __forceinline__ void ln16(float* x, const float* GB, int c0) {
    float s = 0.f, ss = 0.f;
#pragma unroll
    for (int j = 0; j < 16; j++) { s += x[j]; ss += x[j] * x[j]; }
    s = qred(s); ss = qred(ss);
    float mu = s * (1.f / 64.f);
    float rstd = rsqrtf(ss * (1.f / 64.f) - mu * mu + LN_EPS);
#pragma unroll
    for (int j = 0; j < 16; j++)
        x[j] = (x[j] - mu) * rstd * GB[c0 + j] + GB[64 + c0 + j];
}

// pass1 smem (words): KN/KT 4608, PJ 4608, VT 4608, GB 128
#define P1_KN 0
#define P1_PJ 4608
#define P1_VT 9216
#define P1_GB 13824
#define P1_BYTES ((13824 + 128) * 4)
// pass2: QN/QP 4608, PJ/STG 4608, KVT 4608, DEN 128, GB 128
#define P2_QN 0
#define P2_PJ 4608
#define P2_KVT 9216
#define P2_DEN 13824
#define P2_GB 13952
#define P2_BYTES ((13952 + 128) * 4)

// ---------------------------------------------------------------------------
// Pass 1: CTA = 64 tokens. LN+L2(k)->KN, LN(v)->VT,
//   GEMM1 kp=featexp(KN@PJ^T)->g_kp+KT(overlay KN), GEMM2 part=KT@VT^T.
// ---------------------------------------------------------------------------
extern "C" __global__ void __launch_bounds__(256, 4) fa_pass1(
    const float* __restrict__ k, const float* __restrict__ v,
    const float* __restrict__ proj, const float* __restrict__ gamma,
    const float* __restrict__ beta)
{
    extern __shared__ uint32_t sm[];
    uint32_t* KN = sm + P1_KN;
    uint32_t* PJ = sm + P1_PJ;
    uint32_t* VT = sm + P1_VT;
    float* GB = (float*)(sm + P1_GB);

    const int tid = threadIdx.x, lane = tid & 31, wid = tid >> 5;
    const int bh = blockIdx.y, tile = blockIdx.x, t0 = tile * 64;
    const int t = tid >> 2, c0 = (tid & 3) * 16;

    // stage k row segment into regs before the smem-fill sync
    float x[16];
    {
        const float* kr = k + ((size_t)(bh * TV + t0 + t)) * 64 + c0;
#pragma unroll
        for (int i = 0; i < 4; i++) *(float4*)(x + 4 * i) = *(const float4*)(kr + 4 * i);
    }
    if (tid < 64) GB[tid] = gamma[tid];
    else if (tid < 128) GB[tid] = beta[tid - 64];
    for (int i = tid; i < 4096; i += 256) {
        int n = i >> 6, m = i & 63;
        PJ[m * W + n] = packhl(proj[i]);
    }
    __syncthreads();   // GB ready

    // LN + L2 of k -> KN[t][c]
    ln16(x, GB, c0);
    {
        float n2 = 0.f;
#pragma unroll
        for (int j = 0; j < 16; j++) n2 += x[j] * x[j];
        n2 = qred(n2);
        float inv = 1.f / fmaxf(sqrtf(n2), 1e-12f);
#pragma unroll
        for (int j = 0; j < 16; j++) KN[t * W + c0 + j] = packhl(x[j] * inv);
    }
    // LN of v -> VT[c][t] (transposed)
    {
        const float* vr = v + ((size_t)(bh * TV + t0 + t)) * 64 + c0;
#pragma unroll
        for (int i = 0; i < 4; i++) *(float4*)(x + 4 * i) = *(const float4*)(vr + 4 * i);
        ln16(x, GB, c0);
#pragma unroll
        for (int j = 0; j < 16; j++) VT[(c0 + j) * W + t] = packhl(x[j]);
    }
    __syncthreads();   // KN, VT, PJ ready

    const int r = lane >> 2, qk = (lane & 3) * 2;
    const int mb = wid & 3, nh = wid >> 2;
    const int tr = mb * 16 + r;

    // GEMM1: D1[t][m] = KN @ PJ^T (64x64x64)
    float acc[4][4];
#pragma unroll
    for (int f = 0; f < 4; f++)
#pragma unroll
        for (int j = 0; j < 4; j++) acc[f][j] = 0.f;
#pragma unroll
    for (int ks = 0; ks < 4; ks++) {
        Afrag A = lda(KN, tr, ks * 16 + qk);
#pragma unroll
        for (int f = 0; f < 4; f++) {
            Bfrag B = ldb(PJ, nh * 32 + f * 8 + r, ks * 16 + qk);
            mma3(acc[f], A, B);
        }
    }
    __syncthreads();   // all reads of KN done (KT overlays it)

    // Epilogue1: kp = featexp(D1) -> g_kp + KT[m][t]
    {
        uint32_t* KT = KN;
        uint32_t* gkp = g_kp + ((size_t)bh * TV + t0) * 32;
#pragma unroll
        for (int f = 0; f < 4; f++) {
            float x0 = featexp(acc[f][0]), x1 = featexp(acc[f][1]);
            float x2 = featexp(acc[f][2]), x3 = featexp(acc[f][3]);
            int c = nh * 32 + f * 8 + qk;
            gkp[tr * 32 + (c >> 1)] = pack2(x0, x1);
            gkp[(tr + 8) * 32 + (c >> 1)] = pack2(x2, x3);
            KT[c * W + tr] = packhl(x0);
            KT[(c + 1) * W + tr] = packhl(x1);
            KT[c * W + tr + 8] = packhl(x2);
            KT[(c + 1) * W + tr + 8] = packhl(x3);
        }
    }
    __syncthreads();

    // GEMM2: D2[m][n] = sum_t KT[m][t] * VT[n][t] (64x64x64)
    float acc2[4][4];
#pragma unroll
    for (int f = 0; f < 4; f++)
#pragma unroll
        for (int j = 0; j < 4; j++) acc2[f][j] = 0.f;
#pragma unroll
    for (int ks = 0; ks < 4; ks++) {
        Afrag A = lda(KN /*=KT*/, tr, ks * 16 + qk);
#pragma unroll
        for (int f = 0; f < 4; f++) {
            Bfrag B = ldb(VT, nh * 32 + f * 8 + r, ks * 16 + qk);
            mma3(acc2[f], A, B);
        }
    }
    float* gp = g_part + (size_t)(bh * 128 + tile) * 4096;
#pragma unroll
    for (int f = 0; f < 4; f++) {
        int n = nh * 32 + f * 8 + qk;
        *(float2*)(gp + tr * 64 + n) = make_float2(acc2[f][0], acc2[f][1]);
        *(float2*)(gp + (tr + 8) * 64 + n) = make_float2(acc2[f][2], acc2[f][3]);
    }
}

// ---------------------------------------------------------------------------
extern "C" __global__ void __launch_bounds__(256) fa_reduce()
{
    const int tid = blockIdx.x * 256 + threadIdx.x;   // 0 .. 32767
    const int bh = tid >> 10, e4 = tid & 1023;
    const float4* p = (const float4*)(g_part + (size_t)bh * 128 * 4096) + e4;
    float4 s = make_float4(0.f, 0.f, 0.f, 0.f);
#pragma unroll 8
    for (int c = 0; c < 128; ++c) {
        float4 a = p[(size_t)c * 1024];
        s.x += a.x; s.y += a.y; s.z += a.z; s.w += a.w;
    }
    ((float4*)g_kv)[tid] = make_float4(s.x * 0.1f, s.y * 0.1f, s.z * 0.1f, s.w * 0.1f);
}

// ---------------------------------------------------------------------------
// Pass 2: LN+L2(q)->QN, GEMM3 qp=featexp(QN@PJ^T) (QP overlays QN),
//   denom=qp.kp, GEMM4 qkv=QP@KVT^T, scale+final LN -> out
// ---------------------------------------------------------------------------
extern "C" __global__ void __launch_bounds__(256, 4) fa_pass2(
    const float* __restrict__ q, const float* __restrict__ proj,
    const float* __restrict__ gamma, const float* __restrict__ beta,
    float* __restrict__ out)
{
    extern __shared__ uint32_t sm[];
    uint32_t* QN = sm + P2_QN;
    uint32_t* PJ = sm + P2_PJ;
    uint32_t* KVT = sm + P2_KVT;
    float* DEN = (float*)(sm + P2_DEN);
    float* GB = (float*)(sm + P2_GB);

    const int tid = threadIdx.x, lane = tid & 31, wid = tid >> 5;
    const int bh = blockIdx.y, tile = blockIdx.x, t0 = tile * 64;
    const int t = tid >> 2, c0 = (tid & 3) * 16;

    float x[16];
    {
        const float* qr = q + ((size_t)(bh * TV + t0 + t)) * 64 + c0;
#pragma unroll
        for (int i = 0; i < 4; i++) *(float4*)(x + 4 * i) = *(const float4*)(qr + 4 * i);
    }
    if (tid < 64) GB[tid] = gamma[tid];
    else if (tid < 128) GB[tid] = beta[tid - 64];
    for (int i = tid; i < 4096; i += 256) {
        int n = i >> 6, m = i & 63;
        PJ[m * W + n] = packhl(proj[i]);
    }
    {
        const float* kvg = g_kv + (size_t)bh * 4096;
        for (int i = tid; i < 4096; i += 256) {
            int m = i >> 6, n = i & 63;
            KVT[n * W + m] = packhl(kvg[i]);
        }
    }
    __syncthreads();

    // LN + L2 of q -> QN
    ln16(x, GB, c0);
    {
        float n2 = 0.f;
#pragma unroll
        for (int j = 0; j < 16; j++) n2 += x[j] * x[j];
        n2 = qred(n2);
        float inv = 1.f / fmaxf(sqrtf(n2), 1e-12f);
#pragma unroll
        for (int j = 0; j < 16; j++) QN[t * W + c0 + j] = packhl(x[j] * inv);
    }
    __syncthreads();

    const int r = lane >> 2, qk = (lane & 3) * 2;
    const int mb = wid & 3, nh = wid >> 2;
    const int tr = mb * 16 + r;

    // GEMM3: D3[t][m] = QN @ PJ^T
    float acc[4][4];
#pragma unroll
    for (int f = 0; f < 4; f++)
#pragma unroll
        for (int j = 0; j < 4; j++) acc[f][j] = 0.f;
#pragma unroll
    for (int ks = 0; ks < 4; ks++) {
        Afrag A = lda(QN, tr, ks * 16 + qk);
#pragma unroll
        for (int f = 0; f < 4; f++) {
            Bfrag B = ldb(PJ, nh * 32 + f * 8 + r, ks * 16 + qk);
            mma3(acc[f], A, B);
        }
    }
    __syncthreads();   // QN reads done (QP overlays)

    // Epilogue3: qp = featexp(D3) -> QP; denom partials vs g_kp
    {
        uint32_t* QP = QN;
        const uint32_t* gkp = g_kp + ((size_t)bh * TV + t0) * 32;
        float den0 = 0.f, den1 = 0.f;
#pragma unroll
        for (int f = 0; f < 4; f++) {
            float x0 = featexp(acc[f][0]), x1 = featexp(acc[f][1]);
            float x2 = featexp(acc[f][2]), x3 = featexp(acc[f][3]);
            int c = nh * 32 + f * 8 + qk;
            QP[tr * W + c] = packhl(x0);
            QP[tr * W + c + 1] = packhl(x1);
            QP[(tr + 8) * W + c] = packhl(x2);
            QP[(tr + 8) * W + c + 1] = packhl(x3);
            float2 k0 = unpk2(gkp[tr * 32 + (c >> 1)]);
            float2 k1 = unpk2(gkp[(tr + 8) * 32 + (c >> 1)]);
            den0 += x0 * k0.x + x1 * k0.y;
            den1 += x2 * k1.x + x3 * k1.y;
        }
        den0 = qred(den0);
        den1 = qred(den1);
        if ((lane & 3) == 0) { DEN[nh * 64 + tr] = den0; DEN[nh * 64 + tr + 8] = den1; }
    }
    __syncthreads();

    // GEMM4: D4[t][n] = QP @ KVT^T
    float acc2[4][4];
#pragma unroll
    for (int f = 0; f < 4; f++)
#pragma unroll
        for (int j = 0; j < 4; j++) acc2[f][j] = 0.f;
#pragma unroll
    for (int ks = 0; ks < 4; ks++) {
        Afrag A = lda(QN /*=QP*/, tr, ks * 16 + qk);
#pragma unroll
        for (int f = 0; f < 4; f++) {
            Bfrag B = ldb(KVT, nh * 32 + f * 8 + r, ks * 16 + qk);
            mma3(acc2[f], A, B);
        }
    }
    // Epilogue4: x = 0.1*D4/den -> STG (overlays PJ; PJ reads done pre-GEMM4 sync)
    {
        float* STG = (float*)PJ;
        float s0 = 0.1f / fmaxf(DEN[tr] + DEN[64 + tr], DEN_EPS);
        float s1 = 0.1f / fmaxf(DEN[tr + 8] + DEN[64 + tr + 8], DEN_EPS);
#pragma unroll
        for (int f = 0; f < 4; f++) {
            int c = nh * 32 + f * 8 + qk;
            *(float2*)(STG + tr * 68 + c) = make_float2(acc2[f][0] * s0, acc2[f][1] * s0);
            *(float2*)(STG + (tr + 8) * 68 + c) = make_float2(acc2[f][2] * s1, acc2[f][3] * s1);
        }
    }
    __syncthreads();

    // Final LN (quad scheme) -> out
    {
        const float* STG = (const float*)PJ;
#pragma unroll
        for (int i = 0; i < 4; i++) *(float4*)(x + 4 * i) = *(const float4*)(STG + t * 68 + c0 + 4 * i);
        ln16(x, GB, c0);
        float* ob = out + ((size_t)(bh * TV + t0 + t)) * 64 + c0;
#pragma unroll
        for (int i = 0; i < 4; i++) *(float4*)(ob + 4 * i) = *(const float4*)(x + 4 * i);
    }
}

// ---------------------------------------------------------------------------
extern "C" void kernel_launch(void* const* d_in, const int* in_sizes, int n_in,
                              void* d_out, int out_size)
{
    const float* q     = (const float*)d_in[0];
    const float* k     = (const float*)d_in[1];
    const float* v     = (const float*)d_in[2];
    const float* proj  = (const float*)d_in[3];
    const float* gamma = (const float*)d_in[4];
    const float* beta  = (const float*)d_in[5];
    float* out = (float*)d_out;

    cudaFuncSetAttribute(fa_pass1, cudaFuncAttributeMaxDynamicSharedMemorySize, P1_BYTES);
    cudaFuncSetAttribute(fa_pass2, cudaFuncAttributeMaxDynamicSharedMemorySize, P2_BYTES);

    fa_pass1<<<dim3(128, BHV), 256, P1_BYTES>>>(k, v, proj, gamma, beta);
    fa_reduce<<<128, 256>>>();
    fa_pass2<<<dim3(128, BHV), 256, P2_BYTES>>>(q, proj, gamma, beta, out);
}

// round 5
// speedup vs baseline: 1.9223x; 1.1966x over previous
#include <cuda_runtime.h>
#include <cuda_bf16.h>
#include <cstdint>

#define TV 8192
#define BHV 32
#define LN_EPS 1e-5f
#define DEN_EPS 1e-6f
#define RS  72      // row stride in bf16 elems
#define RSB 144     // row stride bytes
#define PL  9216    // one 64xRS bf16 plane, bytes

// Scratch (allocation-free)
__device__ uint32_t g_kp[(size_t)BHV * TV * 32];      // 32 MB kp 2xbf16 [bh][t][m/2]
__device__ float    g_part[(size_t)BHV * 128 * 4096]; // 64 MB partial kv
__device__ float    g_kv[(size_t)BHV * 4096];

// ---------------- helpers ----------------
__device__ __forceinline__ uint32_t smem_u32(const void* p) {
    uint32_t a;
    asm("{ .reg .u64 t; cvta.to.shared.u64 t, %1; cvt.u32.u64 %0, t; }" : "=r"(a) : "l"(p));
    return a;
}
__device__ __forceinline__ float featexp(float x) {
    return __expf(fminf(fmaxf(x, -15.f), 15.f)) * 0.1f;
}
__device__ __forceinline__ float qred(float v) {
    v += __shfl_xor_sync(0xffffffffu, v, 1);
    v += __shfl_xor_sync(0xffffffffu, v, 2);
    return v;
}
__device__ __forceinline__ uint32_t pack2(float x, float y) {
    __nv_bfloat162 b = __floats2bfloat162_rn(x, y);
    return *(uint32_t*)&b;
}
__device__ __forceinline__ float2 unpk2(uint32_t p) {
    __nv_bfloat162 b = *(__nv_bfloat162*)&p;
    return make_float2(__bfloat162float(b.x), __bfloat162float(b.y));
}
// split (a,b) into hi/lo bf16-pair words
__device__ __forceinline__ void packhl2(float a, float b, uint32_t& hi, uint32_t& lo) {
    __nv_bfloat16 ha = __float2bfloat16_rn(a), hb = __float2bfloat16_rn(b);
    __nv_bfloat16 la = __float2bfloat16_rn(a - __bfloat162float(ha));
    __nv_bfloat16 lb = __float2bfloat16_rn(b - __bfloat162float(hb));
    hi = (uint32_t)__bfloat16_as_ushort(ha) | ((uint32_t)__bfloat16_as_ushort(hb) << 16);
    lo = (uint32_t)__bfloat16_as_ushort(la) | ((uint32_t)__bfloat16_as_ushort(lb) << 16);
}
__device__ __forceinline__ void ldsm4(uint32_t* r, uint32_t a) {
    asm volatile("ldmatrix.sync.aligned.m8n8.x4.shared.b16 {%0,%1,%2,%3}, [%4];"
        : "=r"(r[0]), "=r"(r[1]), "=r"(r[2]), "=r"(r[3]) : "r"(a));
}
__device__ __forceinline__ void ldsm4t(uint32_t* r, uint32_t a) {
    asm volatile("ldmatrix.sync.aligned.m8n8.x4.trans.shared.b16 {%0,%1,%2,%3}, [%4];"
        : "=r"(r[0]), "=r"(r[1]), "=r"(r[2]), "=r"(r[3]) : "r"(a));
}
__device__ __forceinline__ void mma_bf16(float* c, const uint32_t* a, uint32_t b0, uint32_t b1) {
    asm("mma.sync.aligned.m16n8k16.row.col.f32.bf16.bf16.f32 "
        "{%0,%1,%2,%3},{%4,%5,%6,%7},{%8,%9},{%0,%1,%2,%3};"
        : "+f"(c[0]), "+f"(c[1]), "+f"(c[2]), "+f"(c[3])
        : "r"(a[0]), "r"(a[1]), "r"(a[2]), "r"(a[3]), "r"(b0), "r"(b1));
}
__device__ __forceinline__ void mma3(float* c, const uint32_t* Ah, const uint32_t* Al,
                                     uint32_t bh0, uint32_t bh1, uint32_t bl0, uint32_t bl1) {
    mma_bf16(c, Ah, bh0, bh1);
    mma_bf16(c, Ah, bl0, bl1);
    mma_bf16(c, Al, bh0, bh1);
}
// LN over 16 register values (quad-cooperative)
__device__ __forceinline__ void ln16(float* x, const float* GB, int c0) {
    float s = 0.f, ss = 0.f;
#pragma unroll
    for (int j = 0; j < 16; j++) { s += x[j]; ss += x[j] * x[j]; }
    s = qred(s); ss = qred(ss);
    float mu = s * (1.f / 64.f);
    float rstd = rsqrtf(ss * (1.f / 64.f) - mu * mu + LN_EPS);
#pragma unroll
    for (int j = 0; j < 16; j++)
        x[j] = (x[j] - mu) * rstd * GB[c0 + j] + GB[64 + c0 + j];
}

// pass1 byte offsets: KN h/l (kp overlays), PJ h/l, VT h/l, GB
#define P1_KNH 0
#define P1_KNL 9216
#define P1_PJH 18432
#define P1_PJL 27648
#define P1_VTH 36864
#define P1_VTL 46080
#define P1_GB  55296
#define P1_BYTES (55296 + 512)
// pass2: QN h/l (qp overlays), PJ h/l (STG overlays), KV h/l, DEN, GB
#define P2_QNH 0
#define P2_QNL 9216
#define P2_PJH 18432
#define P2_PJL 27648
#define P2_KVH 36864
#define P2_KVL 46080
#define P2_DEN 55296
#define P2_GB  55808
#define P2_BYTES (55808 + 512)

// ---------------------------------------------------------------------------
// Pass 1
// ---------------------------------------------------------------------------
extern "C" __global__ void __launch_bounds__(256, 4) fa_pass1(
    const float* __restrict__ k, const float* __restrict__ v,
    const float* __restrict__ proj, const float* __restrict__ gamma,
    const float* __restrict__ beta)
{
    extern __shared__ char sm[];
    const uint32_t sb = smem_u32(sm);
    float* GB = (float*)(sm + P1_GB);

    const int tid = threadIdx.x, lane = tid & 31, wid = tid >> 5;
    const int bh = blockIdx.y, tile = blockIdx.x, t0 = tile * 64;
    const int t = tid >> 2, c0 = (tid & 3) * 16;

    float x[16];
    {
        const float* kr = k + ((size_t)(bh * TV + t0 + t)) * 64 + c0;
#pragma unroll
        for (int i = 0; i < 4; i++) *(float4*)(x + 4 * i) = *(const float4*)(kr + 4 * i);
    }
    if (tid < 64) GB[tid] = gamma[tid];
    else if (tid < 128) GB[tid] = beta[tid - 64];
    // PJ[m][n] planes (rows m, cols n=k of GEMM1)
    for (int i = tid; i < 2048; i += 256) {
        int m = i & 63, n2 = (i >> 6) * 2;
        uint32_t hi, lo;
        packhl2(proj[n2 * 64 + m], proj[(n2 + 1) * 64 + m], hi, lo);
        *(uint32_t*)(sm + P1_PJH + m * RSB + n2 * 2) = hi;
        *(uint32_t*)(sm + P1_PJL + m * RSB + n2 * 2) = lo;
    }
    __syncthreads();   // GB ready

    // LN + L2 of k -> KN[t][k]
    ln16(x, GB, c0);
    {
        float n2 = 0.f;
#pragma unroll
        for (int j = 0; j < 16; j++) n2 += x[j] * x[j];
        n2 = qred(n2);
        float inv = 1.f / fmaxf(sqrtf(n2), 1e-12f);
#pragma unroll
        for (int jj = 0; jj < 8; jj++) {
            uint32_t hi, lo;
            packhl2(x[2 * jj] * inv, x[2 * jj + 1] * inv, hi, lo);
            *(uint32_t*)(sm + P1_KNH + t * RSB + (c0 + 2 * jj) * 2) = hi;
            *(uint32_t*)(sm + P1_KNL + t * RSB + (c0 + 2 * jj) * 2) = lo;
        }
    }
    // LN of v -> VT[t][n] (natural layout)
    {
        const float* vr = v + ((size_t)(bh * TV + t0 + t)) * 64 + c0;
#pragma unroll
        for (int i = 0; i < 4; i++) *(float4*)(x + 4 * i) = *(const float4*)(vr + 4 * i);
        ln16(x, GB, c0);
#pragma unroll
        for (int jj = 0; jj < 8; jj++) {
            uint32_t hi, lo;
            packhl2(x[2 * jj], x[2 * jj + 1], hi, lo);
            *(uint32_t*)(sm + P1_VTH + t * RSB + (c0 + 2 * jj) * 2) = hi;
            *(uint32_t*)(sm + P1_VTL + t * RSB + (c0 + 2 * jj) * 2) = lo;
        }
    }
    __syncthreads();

    const int r = lane >> 2, qk = (lane & 3) * 2;
    const int mb = wid & 3, nh = wid >> 2;
    const int tr = mb * 16 + r;
    const int l7 = lane & 7, l8 = (lane >> 3) & 1, l16 = (lane >> 4) & 1;

    // GEMM1: D1[t][m] = KN @ PJ^T
    float acc[4][4];
#pragma unroll
    for (int f = 0; f < 4; f++)
#pragma unroll
        for (int j = 0; j < 4; j++) acc[f][j] = 0.f;
    {
        uint32_t aH = sb + P1_KNH + (mb * 16 + l7 + l8 * 8) * RSB + l16 * 16;
        uint32_t bH = sb + P1_PJH + (nh * 32 + l7 + l16 * 8) * RSB + l8 * 16;
#pragma unroll
        for (int ks = 0; ks < 4; ks++) {
            uint32_t Ah[4], Al[4];
            ldsm4(Ah, aH + ks * 32);
            ldsm4(Al, aH + PL + ks * 32);
#pragma unroll
            for (int f2 = 0; f2 < 2; f2++) {
                uint32_t Bh[4], Bl[4];
                ldsm4(Bh, bH + f2 * 16 * RSB + ks * 32);
                ldsm4(Bl, bH + PL + f2 * 16 * RSB + ks * 32);
                mma3(acc[f2 * 2],     Ah, Al, Bh[0], Bh[1], Bl[0], Bl[1]);
                mma3(acc[f2 * 2 + 1], Ah, Al, Bh[2], Bh[3], Bl[2], Bl[3]);
            }
        }
    }
    __syncthreads();   // KN reads done (kp overlays)

    // Epilogue1: kp = featexp(D1) -> g_kp + kp planes [t][m]
    {
        uint32_t* gkp = g_kp + ((size_t)bh * TV + t0) * 32;
#pragma unroll
        for (int f = 0; f < 4; f++) {
            float x0 = featexp(acc[f][0]), x1 = featexp(acc[f][1]);
            float x2 = featexp(acc[f][2]), x3 = featexp(acc[f][3]);
            int c = nh * 32 + f * 8 + qk;
            gkp[tr * 32 + (c >> 1)] = pack2(x0, x1);
            gkp[(tr + 8) * 32 + (c >> 1)] = pack2(x2, x3);
            uint32_t hi, lo;
            packhl2(x0, x1, hi, lo);
            *(uint32_t*)(sm + P1_KNH + tr * RSB + c * 2) = hi;
            *(uint32_t*)(sm + P1_KNL + tr * RSB + c * 2) = lo;
            packhl2(x2, x3, hi, lo);
            *(uint32_t*)(sm + P1_KNH + (tr + 8) * RSB + c * 2) = hi;
            *(uint32_t*)(sm + P1_KNL + (tr + 8) * RSB + c * 2) = lo;
        }
    }
    __syncthreads();

    // GEMM2: D2[m][n] = sum_t kp[t][m] * vn[t][n]  (both via ldmatrix.trans)
    float acc2[4][4];
#pragma unroll
    for (int f = 0; f < 4; f++)
#pragma unroll
        for (int j = 0; j < 4; j++) acc2[f][j] = 0.f;
    {
        uint32_t a2 = sb + P1_KNH + (l7 + l16 * 8) * RSB + (mb * 16 + l8 * 8) * 2;
        uint32_t b2 = sb + P1_VTH + (l7 + l8 * 8) * RSB + (nh * 32 + l16 * 8) * 2;
#pragma unroll
        for (int ks = 0; ks < 4; ks++) {
            uint32_t Ah[4], Al[4];
            ldsm4t(Ah, a2 + ks * 16 * RSB);
            ldsm4t(Al, a2 + PL + ks * 16 * RSB);
#pragma unroll
            for (int f2 = 0; f2 < 2; f2++) {
                uint32_t Bh[4], Bl[4];
                ldsm4t(Bh, b2 + f2 * 32 + ks * 16 * RSB);
                ldsm4t(Bl, b2 + PL + f2 * 32 + ks * 16 * RSB);
                mma3(acc2[f2 * 2],     Ah, Al, Bh[0], Bh[1], Bl[0], Bl[1]);
                mma3(acc2[f2 * 2 + 1], Ah, Al, Bh[2], Bh[3], Bl[2], Bl[3]);
            }
        }
    }
    float* gp = g_part + (size_t)(bh * 128 + tile) * 4096;
#pragma unroll
    for (int f = 0; f < 4; f++) {
        int n = nh * 32 + f * 8 + qk;
        *(float2*)(gp + tr * 64 + n) = make_float2(acc2[f][0], acc2[f][1]);
        *(float2*)(gp + (tr + 8) * 64 + n) = make_float2(acc2[f][2], acc2[f][3]);
    }
}

// ---------------------------------------------------------------------------
extern "C" __global__ void __launch_bounds__(256) fa_reduce()
{
    const int tid = blockIdx.x * 256 + threadIdx.x;   // 0 .. 32767
    const int bh = tid >> 10, e4 = tid & 1023;
    const float4* p = (const float4*)(g_part + (size_t)bh * 128 * 4096) + e4;
    float4 s = make_float4(0.f, 0.f, 0.f, 0.f);
#pragma unroll 8
    for (int c = 0; c < 128; ++c) {
        float4 a = p[(size_t)c * 1024];
        s.x += a.x; s.y += a.y; s.z += a.z; s.w += a.w;
    }
    ((float4*)g_kv)[tid] = make_float4(s.x * 0.1f, s.y * 0.1f, s.z * 0.1f, s.w * 0.1f);
}

// ---------------------------------------------------------------------------
// Pass 2
// ---------------------------------------------------------------------------
extern "C" __global__ void __launch_bounds__(256, 4) fa_pass2(
    const float* __restrict__ q, const float* __restrict__ proj,
    const float* __restrict__ gamma, const float* __restrict__ beta,
    float* __restrict__ out)
{
    extern __shared__ char sm[];
    const uint32_t sb = smem_u32(sm);
    float* DEN = (float*)(sm + P2_DEN);
    float* GB  = (float*)(sm + P2_GB);

    const int tid = threadIdx.x, lane = tid & 31, wid = tid >> 5;
    const int bh = blockIdx.y, tile = blockIdx.x, t0 = tile * 64;
    const int t = tid >> 2, c0 = (tid & 3) * 16;

    float x[16];
    {
        const float* qr = q + ((size_t)(bh * TV + t0 + t)) * 64 + c0;
#pragma unroll
        for (int i = 0; i < 4; i++) *(float4*)(x + 4 * i) = *(const float4*)(qr + 4 * i);
    }
    if (tid < 64) GB[tid] = gamma[tid];
    else if (tid < 128) GB[tid] = beta[tid - 64];
    for (int i = tid; i < 2048; i += 256) {
        int m = i & 63, n2 = (i >> 6) * 2;
        uint32_t hi, lo;
        packhl2(proj[n2 * 64 + m], proj[(n2 + 1) * 64 + m], hi, lo);
        *(uint32_t*)(sm + P2_PJH + m * RSB + n2 * 2) = hi;
        *(uint32_t*)(sm + P2_PJL + m * RSB + n2 * 2) = lo;
    }
    {   // kv[m][n] natural planes
        const float* kvg = g_kv + (size_t)bh * 4096;
        for (int i = tid; i < 2048; i += 256) {
            int m = i >> 5, n2 = (i & 31) * 2;
            uint32_t hi, lo;
            packhl2(kvg[m * 64 + n2], kvg[m * 64 + n2 + 1], hi, lo);
            *(uint32_t*)(sm + P2_KVH + m * RSB + n2 * 2) = hi;
            *(uint32_t*)(sm + P2_KVL + m * RSB + n2 * 2) = lo;
        }
    }
    __syncthreads();

    // LN + L2 of q -> QN[t][k]
    ln16(x, GB, c0);
    {
        float n2 = 0.f;
#pragma unroll
        for (int j = 0; j < 16; j++) n2 += x[j] * x[j];
        n2 = qred(n2);
        float inv = 1.f / fmaxf(sqrtf(n2), 1e-12f);
#pragma unroll
        for (int jj = 0; jj < 8; jj++) {
            uint32_t hi, lo;
            packhl2(x[2 * jj] * inv, x[2 * jj + 1] * inv, hi, lo);
            *(uint32_t*)(sm + P2_QNH + t * RSB + (c0 + 2 * jj) * 2) = hi;
            *(uint32_t*)(sm + P2_QNL + t * RSB + (c0 + 2 * jj) * 2) = lo;
        }
    }
    __syncthreads();

    const int r = lane >> 2, qk = (lane & 3) * 2;
    const int mb = wid & 3, nh = wid >> 2;
    const int tr = mb * 16 + r;
    const int l7 = lane & 7, l8 = (lane >> 3) & 1, l16 = (lane >> 4) & 1;

    // GEMM3: D3[t][m] = QN @ PJ^T
    float acc[4][4];
#pragma unroll
    for (int f = 0; f < 4; f++)
#pragma unroll
        for (int j = 0; j < 4; j++) acc[f][j] = 0.f;
    {
        uint32_t aH = sb + P2_QNH + (mb * 16 + l7 + l8 * 8) * RSB + l16 * 16;
        uint32_t bH = sb + P2_PJH + (nh * 32 + l7 + l16 * 8) * RSB + l8 * 16;
#pragma unroll
        for (int ks = 0; ks < 4; ks++) {
            uint32_t Ah[4], Al[4];
            ldsm4(Ah, aH + ks * 32);
            ldsm4(Al, aH + PL + ks * 32);
#pragma unroll
            for (int f2 = 0; f2 < 2; f2++) {
                uint32_t Bh[4], Bl[4];
                ldsm4(Bh, bH + f2 * 16 * RSB + ks * 32);
                ldsm4(Bl, bH + PL + f2 * 16 * RSB + ks * 32);
                mma3(acc[f2 * 2],     Ah, Al, Bh[0], Bh[1], Bl[0], Bl[1]);
                mma3(acc[f2 * 2 + 1], Ah, Al, Bh[2], Bh[3], Bl[2], Bl[3]);
            }
        }
    }
    __syncthreads();   // QN reads done (qp overlays)

    // Epilogue3: qp = featexp -> QN overlay [t][m]; denom partials vs g_kp
    {
        const uint32_t* gkp = g_kp + ((size_t)bh * TV + t0) * 32;
        float den0 = 0.f, den1 = 0.f;
#pragma unroll
        for (int f = 0; f < 4; f++) {
            float x0 = featexp(acc[f][0]), x1 = featexp(acc[f][1]);
            float x2 = featexp(acc[f][2]), x3 = featexp(acc[f][3]);
            int c = nh * 32 + f * 8 + qk;
            uint32_t hi, lo;
            packhl2(x0, x1, hi, lo);
            *(uint32_t*)(sm + P2_QNH + tr * RSB + c * 2) = hi;
            *(uint32_t*)(sm + P2_QNL + tr * RSB + c * 2) = lo;
            packhl2(x2, x3, hi, lo);
            *(uint32_t*)(sm + P2_QNH + (tr + 8) * RSB + c * 2) = hi;
            *(uint32_t*)(sm + P2_QNL + (tr + 8) * RSB + c * 2) = lo;
            float2 k0 = unpk2(gkp[tr * 32 + (c >> 1)]);
            float2 k1 = unpk2(gkp[(tr + 8) * 32 + (c >> 1)]);
            den0 += x0 * k0.x + x1 * k0.y;
            den1 += x2 * k1.x + x3 * k1.y;
        }
        den0 = qred(den0);
        den1 = qred(den1);
        if ((lane & 3) == 0) { DEN[nh * 64 + tr] = den0; DEN[nh * 64 + tr + 8] = den1; }
    }
    __syncthreads();

    // GEMM4: D4[t][n] = qp @ kv  (A natural, B via .trans on kv[m][n])
    float acc2[4][4];
#pragma unroll
    for (int f = 0; f < 4; f++)
#pragma unroll
        for (int j = 0; j < 4; j++) acc2[f][j] = 0.f;
    {
        uint32_t aH = sb + P2_QNH + (mb * 16 + l7 + l8 * 8) * RSB + l16 * 16;
        uint32_t b2 = sb + P2_KVH + (l7 + l8 * 8) * RSB + (nh * 32 + l16 * 8) * 2;
#pragma unroll
        for (int ks = 0; ks < 4; ks++) {
            uint32_t Ah[4], Al[4];
            ldsm4(Ah, aH + ks * 32);
            ldsm4(Al, aH + PL + ks * 32);
#pragma unroll
            for (int f2 = 0; f2 < 2; f2++) {
                uint32_t Bh[4], Bl[4];
                ldsm4t(Bh, b2 + f2 * 32 + ks * 16 * RSB);
                ldsm4t(Bl, b2 + PL + f2 * 32 + ks * 16 * RSB);
                mma3(acc2[f2 * 2],     Ah, Al, Bh[0], Bh[1], Bl[0], Bl[1]);
                mma3(acc2[f2 * 2 + 1], Ah, Al, Bh[2], Bh[3], Bl[2], Bl[3]);
            }
        }
    }
    // Epilogue4: x = 0.1*D4/den -> STG f32 (overlays PJ planes, stride 68)
    {
        float* STG = (float*)(sm + P2_PJH);
        float s0 = 0.1f / fmaxf(DEN[tr] + DEN[64 + tr], DEN_EPS);
        float s1 = 0.1f / fmaxf(DEN[tr + 8] + DEN[64 + tr + 8], DEN_EPS);
#pragma unroll
        for (int f = 0; f < 4; f++) {
            int c = nh * 32 + f * 8 + qk;
            *(float2*)(STG + tr * 68 + c) = make_float2(acc2[f][0] * s0, acc2[f][1] * s0);
            *(float2*)(STG + (tr + 8) * 68 + c) = make_float2(acc2[f][2] * s1, acc2[f][3] * s1);
        }
    }
    __syncthreads();

    // Final LN -> out
    {
        const float* STG = (const float*)(sm + P2_PJH);
#pragma unroll
        for (int i = 0; i < 4; i++)
            *(float4*)(x + 4 * i) = *(const float4*)(STG + t * 68 + c0 + 4 * i);
        ln16(x, GB, c0);
        float* ob = out + ((size_t)(bh * TV + t0 + t)) * 64 + c0;
#pragma unroll
        for (int i = 0; i < 4; i++) *(float4*)(ob + 4 * i) = *(const float4*)(x + 4 * i);
    }
}

// ---------------------------------------------------------------------------
extern "C" void kernel_launch(void* const* d_in, const int* in_sizes, int n_in,
                              void* d_out, int out_size)
{
    const float* q     = (const float*)d_in[0];
    const float* k     = (const float*)d_in[1];
    const float* v     = (const float*)d_in[2];
    const float* proj  = (const float*)d_in[3];
    const float* gamma = (const float*)d_in[4];
    const float* beta  = (const float*)d_in[5];
    float* out = (float*)d_out;

    cudaFuncSetAttribute(fa_pass1, cudaFuncAttributeMaxDynamicSharedMemorySize, P1_BYTES);
    cudaFuncSetAttribute(fa_pass2, cudaFuncAttributeMaxDynamicSharedMemorySize, P2_BYTES);

    fa_pass1<<<dim3(128, BHV), 256, P1_BYTES>>>(k, v, proj, gamma, beta);
    fa_reduce<<<128, 256>>>();
    fa_pass2<<<dim3(128, BHV), 256, P2_BYTES>>>(q, proj, gamma, beta, out);
}

// round 6
// speedup vs baseline: 2.1309x; 1.1085x over previous
#include <cuda_runtime.h>
#include <cuda_bf16.h>
#include <cstdint>

#define TV 8192
#define BHV 32
#define LN_EPS 1e-5f
#define DEN_EPS 1e-6f
#define RSB 144     // plane row stride bytes (72 bf16)
#define PL  9216    // one 64-row plane, bytes
#define TPC 8       // 64-token tiles per CTA

// Scratch (allocation-free)
__device__ uint32_t g_kp[(size_t)BHV * TV * 32];            // 32 MB kp 2xbf16 [bh][t][m/2]
__device__ float    g_part[(size_t)BHV * 16 * 4096];        // 8 MB partial kv
__device__ __align__(16) uint32_t g_pjh[2304];              // packed proj plane [m][n]
__device__ __align__(16) uint32_t g_kvh[(size_t)BHV * 2304];// packed kv hi plane per bh
__device__ __align__(16) uint32_t g_kvl[(size_t)BHV * 2304];// packed kv lo plane per bh

// ---------------- helpers ----------------
__device__ __forceinline__ uint32_t smem_u32(const void* p) {
    uint32_t a;
    asm("{ .reg .u64 t; cvta.to.shared.u64 t, %1; cvt.u32.u64 %0, t; }" : "=r"(a) : "l"(p));
    return a;
}
__device__ __forceinline__ float featexp(float x) {
    return __expf(fminf(fmaxf(x, -15.f), 15.f)) * 0.1f;
}
__device__ __forceinline__ float qred(float v) {
    v += __shfl_xor_sync(0xffffffffu, v, 1);
    v += __shfl_xor_sync(0xffffffffu, v, 2);
    return v;
}
__device__ __forceinline__ uint32_t pack2(float x, float y) {
    __nv_bfloat162 b = __floats2bfloat162_rn(x, y);
    return *(uint32_t*)&b;
}
__device__ __forceinline__ float2 unpk2(uint32_t p) {
    __nv_bfloat162 b = *(__nv_bfloat162*)&p;
    return make_float2(__bfloat162float(b.x), __bfloat162float(b.y));
}
__device__ __forceinline__ void packhl2(float a, float b, uint32_t& hi, uint32_t& lo) {
    __nv_bfloat16 ha = __float2bfloat16_rn(a), hb = __float2bfloat16_rn(b);
    __nv_bfloat16 la = __float2bfloat16_rn(a - __bfloat162float(ha));
    __nv_bfloat16 lb = __float2bfloat16_rn(b - __bfloat162float(hb));
    hi = (uint32_t)__bfloat16_as_ushort(ha) | ((uint32_t)__bfloat16_as_ushort(hb) << 16);
    lo = (uint32_t)__bfloat16_as_ushort(la) | ((uint32_t)__bfloat16_as_ushort(lb) << 16);
}
__device__ __forceinline__ void ldsm4(uint32_t* r, uint32_t a) {
    asm volatile("ldmatrix.sync.aligned.m8n8.x4.shared.b16 {%0,%1,%2,%3}, [%4];"
        : "=r"(r[0]), "=r"(r[1]), "=r"(r[2]), "=r"(r[3]) : "r"(a));
}
__device__ __forceinline__ void ldsm4t(uint32_t* r, uint32_t a) {
    asm volatile("ldmatrix.sync.aligned.m8n8.x4.trans.shared.b16 {%0,%1,%2,%3}, [%4];"
        : "=r"(r[0]), "=r"(r[1]), "=r"(r[2]), "=r"(r[3]) : "r"(a));
}
__device__ __forceinline__ void mma_bf16(float* c, const uint32_t* a, uint32_t b0, uint32_t b1) {
    asm("mma.sync.aligned.m16n8k16.row.col.f32.bf16.bf16.f32 "
        "{%0,%1,%2,%3},{%4,%5,%6,%7},{%8,%9},{%0,%1,%2,%3};"
        : "+f"(c[0]), "+f"(c[1]), "+f"(c[2]), "+f"(c[3])
        : "r"(a[0]), "r"(a[1]), "r"(a[2]), "r"(a[3]), "r"(b0), "r"(b1));
}
__device__ __forceinline__ void mma3(float* c, const uint32_t* Ah, const uint32_t* Al,
                                     uint32_t bh0, uint32_t bh1, uint32_t bl0, uint32_t bl1) {
    mma_bf16(c, Ah, bh0, bh1);
    mma_bf16(c, Ah, bl0, bl1);
    mma_bf16(c, Al, bh0, bh1);
}
__device__ __forceinline__ void ln16(float* x, const float* GB, int c0) {
    float s = 0.f, ss = 0.f;
#pragma unroll
    for (int j = 0; j < 16; j++) { s += x[j]; ss += x[j] * x[j]; }
    s = qred(s); ss = qred(ss);
    float mu = s * (1.f / 64.f);
    float rstd = rsqrtf(ss * (1.f / 64.f) - mu * mu + LN_EPS);
#pragma unroll
    for (int j = 0; j < 16; j++)
        x[j] = (x[j] - mu) * rstd * GB[c0 + j] + GB[64 + c0 + j];
}

// pass1 byte offsets
#define P1_KPH 0       // KN (single plane) overlaid by kp-hi
#define P1_KPL 9216    // kp-lo
#define P1_PJ  18432   // proj hi (single plane)
#define P1_VTH 27648
#define P1_VTL 36864
#define P1_GB  46080
#define P1_BYTES (46080 + 512)
// pass2 byte offsets
#define P2_QNH 0       // QN (single) overlaid by qp-hi; STG overlays QNH+QPL
#define P2_QPL 9216
#define P2_PJ  18432
#define P2_KVH 27648
#define P2_KVL 36864
#define P2_DEN 46080
#define P2_GB  46592
#define P2_BYTES (46592 + 512)

// ---------------------------------------------------------------------------
extern "C" __global__ void fa_setup(const float* __restrict__ proj)
{
    const int tid = threadIdx.x;
    for (int i = tid; i < 2048; i += 256) {
        int m = i & 63, nw = i >> 6;                 // nw: word (2 cols)
        g_pjh[m * 36 + nw] = pack2(proj[(2 * nw) * 64 + m], proj[(2 * nw + 1) * 64 + m]);
    }
}

// ---------------------------------------------------------------------------
// Pass 1: CTA = 512 tokens (8 x 64-tile loop). Per tile:
//   LN+L2(k)->KN, LN(v)->VT planes; GEMM1(single bf16) kp=featexp(KN@PJ^T);
//   kp->g_kp + hi/lo planes; GEMM2(3-term) acc2 += kp^T @ vn.
// ---------------------------------------------------------------------------
extern "C" __global__ void __launch_bounds__(256, 4) fa_pass1(
    const float* __restrict__ k, const float* __restrict__ v,
    const float* __restrict__ gamma, const float* __restrict__ beta)
{
    extern __shared__ char sm[];
    const uint32_t sb = smem_u32(sm);
    float* GB = (float*)(sm + P1_GB);

    const int tid = threadIdx.x, lane = tid & 31, wid = tid >> 5;
    const int bh = blockIdx.y, bx = blockIdx.x;
    const int t = tid >> 2, c0 = (tid & 3) * 16;

    if (tid < 64) GB[tid] = gamma[tid];
    else if (tid < 128) GB[tid] = beta[tid - 64];
    {   // PJ plane copy (pre-packed)
        const uint4* src = (const uint4*)g_pjh;
        uint4* dst = (uint4*)(sm + P1_PJ);
        for (int i = tid; i < 576; i += 256) dst[i] = src[i];
    }
    __syncthreads();

    const int r = lane >> 2, qk = (lane & 3) * 2;
    const int mb = wid & 3, nh = wid >> 2;
    const int tr = mb * 16 + r;
    const int l7 = lane & 7, l8 = (lane >> 3) & 1, l16 = (lane >> 4) & 1;

    // loop-invariant ldmatrix addresses
    const uint32_t aG1 = sb + P1_KPH + (mb * 16 + l7 + l8 * 8) * RSB + l16 * 16;
    const uint32_t bG1 = sb + P1_PJ + (nh * 32 + l7 + l16 * 8) * RSB + l8 * 16;
    const uint32_t aG2 = sb + P1_KPH + (l7 + l16 * 8) * RSB + (mb * 16 + l8 * 8) * 2;
    const uint32_t bG2 = sb + P1_VTH + (l7 + l8 * 8) * RSB + (nh * 32 + l16 * 8) * 2;

    float acc2[4][4];
#pragma unroll
    for (int f = 0; f < 4; f++)
#pragma unroll
        for (int j = 0; j < 4; j++) acc2[f][j] = 0.f;

    for (int it = 0; it < TPC; ++it) {
        const int t0 = (bx * TPC + it) * 64;

        // ---- Phase A: LN(k)+L2 -> KN, LN(v) -> VT ----
        {
            const float* kr = k + ((size_t)(bh * TV + t0 + t)) * 64 + c0;
            const float* vr = v + ((size_t)(bh * TV + t0 + t)) * 64 + c0;
            float xk[16], xv[16];
#pragma unroll
            for (int i = 0; i < 4; i++) *(float4*)(xk + 4 * i) = *(const float4*)(kr + 4 * i);
#pragma unroll
            for (int i = 0; i < 4; i++) *(float4*)(xv + 4 * i) = *(const float4*)(vr + 4 * i);
            ln16(xk, GB, c0);
            float n2 = 0.f;
#pragma unroll
            for (int j = 0; j < 16; j++) n2 += xk[j] * xk[j];
            n2 = qred(n2);
            float inv = 1.f / fmaxf(sqrtf(n2), 1e-12f);
#pragma unroll
            for (int jj = 0; jj < 8; jj++)
                *(uint32_t*)(sm + P1_KPH + t * RSB + (c0 + 2 * jj) * 2) =
                    pack2(xk[2 * jj] * inv, xk[2 * jj + 1] * inv);
            ln16(xv, GB, c0);
#pragma unroll
            for (int jj = 0; jj < 8; jj++) {
                uint32_t hi, lo;
                packhl2(xv[2 * jj], xv[2 * jj + 1], hi, lo);
                *(uint32_t*)(sm + P1_VTH + t * RSB + (c0 + 2 * jj) * 2) = hi;
                *(uint32_t*)(sm + P1_VTL + t * RSB + (c0 + 2 * jj) * 2) = lo;
            }
        }
        __syncthreads();

        // ---- Phase B: GEMM1 single-bf16: D1[t][m] = KN @ PJ^T ----
        float acc[4][4];
#pragma unroll
        for (int f = 0; f < 4; f++)
#pragma unroll
            for (int j = 0; j < 4; j++) acc[f][j] = 0.f;
#pragma unroll
        for (int ks = 0; ks < 4; ks++) {
            uint32_t Ah[4];
            ldsm4(Ah, aG1 + ks * 32);
#pragma unroll
            for (int f2 = 0; f2 < 2; f2++) {
                uint32_t Bh[4];
                ldsm4(Bh, bG1 + f2 * 16 * RSB + ks * 32);
                mma_bf16(acc[f2 * 2],     Ah, Bh[0], Bh[1]);
                mma_bf16(acc[f2 * 2 + 1], Ah, Bh[2], Bh[3]);
            }
        }
        __syncthreads();   // KN reads done (kp overlays)

        // ---- Phase C: kp = featexp(D1) -> g_kp + hi/lo planes ----
        {
            uint32_t* gkp = g_kp + ((size_t)bh * TV + t0) * 32;
#pragma unroll
            for (int f = 0; f < 4; f++) {
                float x0 = featexp(acc[f][0]), x1 = featexp(acc[f][1]);
                float x2 = featexp(acc[f][2]), x3 = featexp(acc[f][3]);
                int c = nh * 32 + f * 8 + qk;
                gkp[tr * 32 + (c >> 1)] = pack2(x0, x1);
                gkp[(tr + 8) * 32 + (c >> 1)] = pack2(x2, x3);
                uint32_t hi, lo;
                packhl2(x0, x1, hi, lo);
                *(uint32_t*)(sm + P1_KPH + tr * RSB + c * 2) = hi;
                *(uint32_t*)(sm + P1_KPL + tr * RSB + c * 2) = lo;
                packhl2(x2, x3, hi, lo);
                *(uint32_t*)(sm + P1_KPH + (tr + 8) * RSB + c * 2) = hi;
                *(uint32_t*)(sm + P1_KPL + (tr + 8) * RSB + c * 2) = lo;
            }
        }
        __syncthreads();

        // ---- Phase D: GEMM2 3-term: acc2[m][n] += kp^T @ vn ----
#pragma unroll
        for (int ks = 0; ks < 4; ks++) {
            uint32_t Ah[4], Al[4];
            ldsm4t(Ah, aG2 + ks * 16 * RSB);
            ldsm4t(Al, aG2 + PL + ks * 16 * RSB);
#pragma unroll
            for (int f2 = 0; f2 < 2; f2++) {
                uint32_t Bh[4], Bl[4];
                ldsm4t(Bh, bG2 + f2 * 32 + ks * 16 * RSB);
                ldsm4t(Bl, bG2 + PL + f2 * 32 + ks * 16 * RSB);
                mma3(acc2[f2 * 2],     Ah, Al, Bh[0], Bh[1], Bl[0], Bl[1]);
                mma3(acc2[f2 * 2 + 1], Ah, Al, Bh[2], Bh[3], Bl[2], Bl[3]);
            }
        }
        __syncthreads();   // protect KN/VT for next iter
    }

    float* gp = g_part + (size_t)(bh * 16 + bx) * 4096;
#pragma unroll
    for (int f = 0; f < 4; f++) {
        int n = nh * 32 + f * 8 + qk;
        *(float2*)(gp + tr * 64 + n) = make_float2(acc2[f][0], acc2[f][1]);
        *(float2*)(gp + (tr + 8) * 64 + n) = make_float2(acc2[f][2], acc2[f][3]);
    }
}

// ---------------------------------------------------------------------------
// Reduce: kv = 0.1 * sum of 16 partials -> packed hi/lo planes per bh
// ---------------------------------------------------------------------------
extern "C" __global__ void __launch_bounds__(256) fa_reduce()
{
    const int tid = blockIdx.x * 256 + threadIdx.x;   // 0 .. 32767
    const int bh = tid >> 10, e4 = tid & 1023;
    const float4* p = (const float4*)(g_part + (size_t)bh * 16 * 4096) + e4;
    float4 s = make_float4(0.f, 0.f, 0.f, 0.f);
#pragma unroll
    for (int c = 0; c < 16; ++c) {
        float4 a = p[(size_t)c * 1024];
        s.x += a.x; s.y += a.y; s.z += a.z; s.w += a.w;
    }
    s.x *= 0.1f; s.y *= 0.1f; s.z *= 0.1f; s.w *= 0.1f;
    const int m = e4 >> 4, n0 = (e4 & 15) * 4;
    const int base = bh * 2304 + m * 36 + (n0 >> 1);
    uint32_t hi, lo;
    packhl2(s.x, s.y, hi, lo);
    g_kvh[base] = hi; g_kvl[base] = lo;
    packhl2(s.z, s.w, hi, lo);
    g_kvh[base + 1] = hi; g_kvl[base + 1] = lo;
}

// ---------------------------------------------------------------------------
// Pass 2: CTA = 512 tokens (8-tile loop).
// ---------------------------------------------------------------------------
extern "C" __global__ void __launch_bounds__(256, 4) fa_pass2(
    const float* __restrict__ q, const float* __restrict__ gamma,
    const float* __restrict__ beta, float* __restrict__ out)
{
    extern __shared__ char sm[];
    const uint32_t sb = smem_u32(sm);
    float* DEN = (float*)(sm + P2_DEN);
    float* GB  = (float*)(sm + P2_GB);

    const int tid = threadIdx.x, lane = tid & 31, wid = tid >> 5;
    const int bh = blockIdx.y, bx = blockIdx.x;
    const int t = tid >> 2, c0 = (tid & 3) * 16;

    if (tid < 64) GB[tid] = gamma[tid];
    else if (tid < 128) GB[tid] = beta[tid - 64];
    {
        const uint4* src = (const uint4*)g_pjh;
        uint4* dst = (uint4*)(sm + P2_PJ);
        for (int i = tid; i < 576; i += 256) dst[i] = src[i];
        const uint4* kh = (const uint4*)(g_kvh + bh * 2304);
        const uint4* kl = (const uint4*)(g_kvl + bh * 2304);
        uint4* dh = (uint4*)(sm + P2_KVH);
        uint4* dl = (uint4*)(sm + P2_KVL);
        for (int i = tid; i < 576; i += 256) { dh[i] = kh[i]; dl[i] = kl[i]; }
    }
    __syncthreads();

    const int r = lane >> 2, qk = (lane & 3) * 2;
    const int mb = wid & 3, nh = wid >> 2;
    const int tr = mb * 16 + r;
    const int l7 = lane & 7, l8 = (lane >> 3) & 1, l16 = (lane >> 4) & 1;

    const uint32_t aG3 = sb + P2_QNH + (mb * 16 + l7 + l8 * 8) * RSB + l16 * 16;
    const uint32_t bG3 = sb + P2_PJ + (nh * 32 + l7 + l16 * 8) * RSB + l8 * 16;
    const uint32_t bG4 = sb + P2_KVH + (l7 + l8 * 8) * RSB + (nh * 32 + l16 * 8) * 2;

    for (int it = 0; it < TPC; ++it) {
        const int t0 = (bx * TPC + it) * 64;
        float x[16];

        // ---- LN + L2 of q -> QN ----
        {
            const float* qr = q + ((size_t)(bh * TV + t0 + t)) * 64 + c0;
#pragma unroll
            for (int i = 0; i < 4; i++) *(float4*)(x + 4 * i) = *(const float4*)(qr + 4 * i);
            ln16(x, GB, c0);
            float n2 = 0.f;
#pragma unroll
            for (int j = 0; j < 16; j++) n2 += x[j] * x[j];
            n2 = qred(n2);
            float inv = 1.f / fmaxf(sqrtf(n2), 1e-12f);
#pragma unroll
            for (int jj = 0; jj < 8; jj++)
                *(uint32_t*)(sm + P2_QNH + t * RSB + (c0 + 2 * jj) * 2) =
                    pack2(x[2 * jj] * inv, x[2 * jj + 1] * inv);
        }
        __syncthreads();

        // ---- GEMM3 single-bf16: D3[t][m] = QN @ PJ^T ----
        float acc[4][4];
#pragma unroll
        for (int f = 0; f < 4; f++)
#pragma unroll
            for (int j = 0; j < 4; j++) acc[f][j] = 0.f;
#pragma unroll
        for (int ks = 0; ks < 4; ks++) {
            uint32_t Ah[4];
            ldsm4(Ah, aG3 + ks * 32);
#pragma unroll
            for (int f2 = 0; f2 < 2; f2++) {
                uint32_t Bh[4];
                ldsm4(Bh, bG3 + f2 * 16 * RSB + ks * 32);
                mma_bf16(acc[f2 * 2],     Ah, Bh[0], Bh[1]);
                mma_bf16(acc[f2 * 2 + 1], Ah, Bh[2], Bh[3]);
            }
        }
        __syncthreads();   // QN reads done (qp overlays)

        // ---- qp = featexp(D3) -> planes; denom vs g_kp ----
        {
            const uint32_t* gkp = g_kp + ((size_t)bh * TV + t0) * 32;
            float den0 = 0.f, den1 = 0.f;
#pragma unroll
            for (int f = 0; f < 4; f++) {
                float x0 = featexp(acc[f][0]), x1 = featexp(acc[f][1]);
                float x2 = featexp(acc[f][2]), x3 = featexp(acc[f][3]);
                int c = nh * 32 + f * 8 + qk;
                uint32_t hi, lo;
                packhl2(x0, x1, hi, lo);
                *(uint32_t*)(sm + P2_QNH + tr * RSB + c * 2) = hi;
                *(uint32_t*)(sm + P2_QPL + tr * RSB + c * 2) = lo;
                packhl2(x2, x3, hi, lo);
                *(uint32_t*)(sm + P2_QNH + (tr + 8) * RSB + c * 2) = hi;
                *(uint32_t*)(sm + P2_QPL + (tr + 8) * RSB + c * 2) = lo;
                float2 k0 = unpk2(gkp[tr * 32 + (c >> 1)]);
                float2 k1 = unpk2(gkp[(tr + 8) * 32 + (c >> 1)]);
                den0 += x0 * k0.x + x1 * k0.y;
                den1 += x2 * k1.x + x3 * k1.y;
            }
            den0 = qred(den0);
            den1 = qred(den1);
            if ((lane & 3) == 0) { DEN[nh * 64 + tr] = den0; DEN[nh * 64 + tr + 8] = den1; }
        }
        __syncthreads();

        // ---- GEMM4 3-term: D4[t][n] = qp @ kv ----
        float acc2[4][4];
#pragma unroll
        for (int f = 0; f < 4; f++)
#pragma unroll
            for (int j = 0; j < 4; j++) acc2[f][j] = 0.f;
#pragma unroll
        for (int ks = 0; ks < 4; ks++) {
            uint32_t Ah[4], Al[4];
            ldsm4(Ah, aG3 + ks * 32);
            ldsm4(Al, aG3 + PL + ks * 32);
#pragma unroll
            for (int f2 = 0; f2 < 2; f2++) {
                uint32_t Bh[4], Bl[4];
                ldsm4t(Bh, bG4 + f2 * 32 + ks * 16 * RSB);
                ldsm4t(Bl, bG4 + PL + f2 * 32 + ks * 16 * RSB);
                mma3(acc2[f2 * 2],     Ah, Al, Bh[0], Bh[1], Bl[0], Bl[1]);
                mma3(acc2[f2 * 2 + 1], Ah, Al, Bh[2], Bh[3], Bl[2], Bl[3]);
            }
        }
        __syncthreads();   // qp reads done (STG overlays QNH+QPL)

        // ---- scale by 0.1/den -> STG ----
        {
            float* STG = (float*)sm;
            float s0 = 0.1f / fmaxf(DEN[tr] + DEN[64 + tr], DEN_EPS);
            float s1 = 0.1f / fmaxf(DEN[tr + 8] + DEN[64 + tr + 8], DEN_EPS);
#pragma unroll
            for (int f = 0; f < 4; f++) {
                int c = nh * 32 + f * 8 + qk;
                *(float2*)(STG + tr * 68 + c) = make_float2(acc2[f][0] * s0, acc2[f][1] * s0);
                *(float2*)(STG + (tr + 8) * 68 + c) = make_float2(acc2[f][2] * s1, acc2[f][3] * s1);
            }
        }
        __syncthreads();

        // ---- final LN -> out ----
        {
            const float* STG = (const float*)sm;
#pragma unroll
            for (int i = 0; i < 4; i++)
                *(float4*)(x + 4 * i) = *(const float4*)(STG + t * 68 + c0 + 4 * i);
            ln16(x, GB, c0);
            float* ob = out + ((size_t)(bh * TV + t0 + t)) * 64 + c0;
#pragma unroll
            for (int i = 0; i < 4; i++) *(float4*)(ob + 4 * i) = *(const float4*)(x + 4 * i);
        }
        __syncthreads();   // STG/QN region reused next iter
    }
}

// ---------------------------------------------------------------------------
extern "C" void kernel_launch(void* const* d_in, const int* in_sizes, int n_in,
                              void* d_out, int out_size)
{
    const float* q     = (const float*)d_in[0];
    const float* k     = (const float*)d_in[1];
    const float* v     = (const float*)d_in[2];
    const float* proj  = (const float*)d_in[3];
    const float* gamma = (const float*)d_in[4];
    const float* beta  = (const float*)d_in[5];
    float* out = (float*)d_out;

    cudaFuncSetAttribute(fa_pass1, cudaFuncAttributeMaxDynamicSharedMemorySize, P1_BYTES);
    cudaFuncSetAttribute(fa_pass2, cudaFuncAttributeMaxDynamicSharedMemorySize, P2_BYTES);

    fa_setup<<<1, 256>>>(proj);
    fa_pass1<<<dim3(16, BHV), 256, P1_BYTES>>>(k, v, gamma, beta);
    fa_reduce<<<128, 256>>>();
    fa_pass2<<<dim3(16, BHV), 256, P2_BYTES>>>(q, gamma, beta, out);
}

// round 9
// speedup vs baseline: 2.3038x; 1.0812x over previous
#include <cuda_runtime.h>
#include <cuda_bf16.h>
#include <cstdint>

#define TV 8192
#define BHV 32
#define LN_EPS 1e-5f
#define DEN_EPS 1e-6f
#define RSB 144     // plane row stride bytes (72 bf16)
#define PL  9216    // one 64-row plane, bytes
#define TPC 8       // 64-token tiles per CTA

// Scratch (allocation-free)
__device__ uint32_t g_kp[(size_t)BHV * TV * 32];            // 32 MB kp 2xbf16 [bh][t][m/2]
__device__ float    g_part[(size_t)BHV * 16 * 4096];        // 8 MB partial kv
__device__ __align__(16) uint32_t g_pjh[2304];              // packed proj plane [m][n]
__device__ __align__(16) uint32_t g_kvh[(size_t)BHV * 2304];
__device__ __align__(16) uint32_t g_kvl[(size_t)BHV * 2304];

// ---------------- helpers ----------------
__device__ __forceinline__ uint32_t smem_u32(const void* p) {
    uint32_t a;
    asm("{ .reg .u64 t; cvta.to.shared.u64 t, %1; cvt.u32.u64 %0, t; }" : "=r"(a) : "l"(p));
    return a;
}
__device__ __forceinline__ float featexp(float x) {
    return __expf(fminf(fmaxf(x, -15.f), 15.f)) * 0.1f;
}
__device__ __forceinline__ float qred(float v) {
    v += __shfl_xor_sync(0xffffffffu, v, 1);
    v += __shfl_xor_sync(0xffffffffu, v, 2);
    return v;
}
__device__ __forceinline__ uint32_t pack2(float x, float y) {
    __nv_bfloat162 b = __floats2bfloat162_rn(x, y);
    return *(uint32_t*)&b;
}
__device__ __forceinline__ float2 unpk2(uint32_t p) {
    __nv_bfloat162 b = *(__nv_bfloat162*)&p;
    return make_float2(__bfloat162float(b.x), __bfloat162float(b.y));
}
__device__ __forceinline__ void packhl2(float a, float b, uint32_t& hi, uint32_t& lo) {
    __nv_bfloat16 ha = __float2bfloat16_rn(a), hb = __float2bfloat16_rn(b);
    __nv_bfloat16 la = __float2bfloat16_rn(a - __bfloat162float(ha));
    __nv_bfloat16 lb = __float2bfloat16_rn(b - __bfloat162float(hb));
    hi = (uint32_t)__bfloat16_as_ushort(ha) | ((uint32_t)__bfloat16_as_ushort(hb) << 16);
    lo = (uint32_t)__bfloat16_as_ushort(la) | ((uint32_t)__bfloat16_as_ushort(lb) << 16);
}
__device__ __forceinline__ void ldsm4(uint32_t* r, uint32_t a) {
    asm volatile("ldmatrix.sync.aligned.m8n8.x4.shared.b16 {%0,%1,%2,%3}, [%4];"
        : "=r"(r[0]), "=r"(r[1]), "=r"(r[2]), "=r"(r[3]) : "r"(a));
}
__device__ __forceinline__ void ldsm4t(uint32_t* r, uint32_t a) {
    asm volatile("ldmatrix.sync.aligned.m8n8.x4.trans.shared.b16 {%0,%1,%2,%3}, [%4];"
        : "=r"(r[0]), "=r"(r[1]), "=r"(r[2]), "=r"(r[3]) : "r"(a));
}
__device__ __forceinline__ void mma_bf16(float* c, const uint32_t* a, uint32_t b0, uint32_t b1) {
    asm("mma.sync.aligned.m16n8k16.row.col.f32.bf16.bf16.f32 "
        "{%0,%1,%2,%3},{%4,%5,%6,%7},{%8,%9},{%0,%1,%2,%3};"
        : "+f"(c[0]), "+f"(c[1]), "+f"(c[2]), "+f"(c[3])
        : "r"(a[0]), "r"(a[1]), "r"(a[2]), "r"(a[3]), "r"(b0), "r"(b1));
}
__device__ __forceinline__ void mma3(float* c, const uint32_t* Ah, const uint32_t* Al,
                                     uint32_t bh0, uint32_t bh1, uint32_t bl0, uint32_t bl1) {
    mma_bf16(c, Ah, bh0, bh1);
    mma_bf16(c, Ah, bl0, bl1);
    mma_bf16(c, Al, bh0, bh1);
}
__device__ __forceinline__ void ln16(float* x, const float* GB, int c0) {
    float s = 0.f, ss = 0.f;
#pragma unroll
    for (int j = 0; j < 16; j++) { s += x[j]; ss += x[j] * x[j]; }
    s = qred(s); ss = qred(ss);
    float mu = s * (1.f / 64.f);
    float rstd = rsqrtf(ss * (1.f / 64.f) - mu * mu + LN_EPS);
#pragma unroll
    for (int j = 0; j < 16; j++)
        x[j] = (x[j] - mu) * rstd * GB[c0 + j] + GB[64 + c0 + j];
}

// pass1 byte offsets (EXACT R6)
#define P1_KPH 0       // KN (single plane) overlaid by kp-hi
#define P1_KPL 9216    // kp-lo
#define P1_PJ  18432   // proj hi (single plane)
#define P1_VTH 27648
#define P1_VTL 36864
#define P1_GB  46080
#define P1_BYTES (46080 + 512)
// pass2 byte offsets (R6 + 2KB PD)
#define P2_QNH 0       // QN single plane, overlaid by qp-hi
#define P2_QPL 9216    // qp-lo
#define P2_PJ  18432
#define P2_KVH 27648
#define P2_KVL 36864
#define P2_DEN 46080
#define P2_PD  46592   // 256 x float2 = 2048B
#define P2_GB  48640
#define P2_BYTES 49152

// ---------------------------------------------------------------------------
extern "C" __global__ void fa_setup(const float* __restrict__ proj)
{
    const int tid = threadIdx.x;
    for (int i = tid; i < 2048; i += 256) {
        int m = i & 63, nw = i >> 6;
        g_pjh[m * 36 + nw] = pack2(proj[(2 * nw) * 64 + m], proj[(2 * nw + 1) * 64 + m]);
    }
}

// ---------------------------------------------------------------------------
// Pass 1: EXACT R6 (proven at 207.6us). CTA = 512 tokens, 8 x 64-token tiles.
// ---------------------------------------------------------------------------
extern "C" __global__ void __launch_bounds__(256, 4) fa_pass1(
    const float* __restrict__ k, const float* __restrict__ v,
    const float* __restrict__ gamma, const float* __restrict__ beta)
{
    extern __shared__ char sm[];
    const uint32_t sb = smem_u32(sm);
    float* GB = (float*)(sm + P1_GB);

    const int tid = threadIdx.x, lane = tid & 31, wid = tid >> 5;
    const int bh = blockIdx.y, bx = blockIdx.x;
    const int t = tid >> 2, c0 = (tid & 3) * 16;

    if (tid < 64) GB[tid] = gamma[tid];
    else if (tid < 128) GB[tid] = beta[tid - 64];
    {
        const uint4* src = (const uint4*)g_pjh;
        uint4* dst = (uint4*)(sm + P1_PJ);
        for (int i = tid; i < 576; i += 256) dst[i] = src[i];
    }
    __syncthreads();

    const int r = lane >> 2, qk = (lane & 3) * 2;
    const int mb = wid & 3, nh = wid >> 2;
    const int tr = mb * 16 + r;
    const int l7 = lane & 7, l8 = (lane >> 3) & 1, l16 = (lane >> 4) & 1;

    const uint32_t aG1 = sb + P1_KPH + (mb * 16 + l7 + l8 * 8) * RSB + l16 * 16;
    const uint32_t bG1 = sb + P1_PJ + (nh * 32 + l7 + l16 * 8) * RSB + l8 * 16;
    const uint32_t aG2 = sb + P1_KPH + (l7 + l16 * 8) * RSB + (mb * 16 + l8 * 8) * 2;
    const uint32_t bG2 = sb + P1_VTH + (l7 + l8 * 8) * RSB + (nh * 32 + l16 * 8) * 2;

    float acc2[4][4];
#pragma unroll
    for (int f = 0; f < 4; f++)
#pragma unroll
        for (int j = 0; j < 4; j++) acc2[f][j] = 0.f;

    for (int it = 0; it < TPC; ++it) {
        const int t0 = (bx * TPC + it) * 64;

        // ---- A: LN(k)+L2 -> KN (single bf16, in KPH plane), LN(v) -> VT hi/lo ----
        {
            const float* kr = k + ((size_t)(bh * TV + t0 + t)) * 64 + c0;
            const float* vr = v + ((size_t)(bh * TV + t0 + t)) * 64 + c0;
            float xk[16], xv[16];
#pragma unroll
            for (int i = 0; i < 4; i++) *(float4*)(xk + 4 * i) = *(const float4*)(kr + 4 * i);
#pragma unroll
            for (int i = 0; i < 4; i++) *(float4*)(xv + 4 * i) = *(const float4*)(vr + 4 * i);
            ln16(xk, GB, c0);
            float n2 = 0.f;
#pragma unroll
            for (int j = 0; j < 16; j++) n2 += xk[j] * xk[j];
            n2 = qred(n2);
            float inv = 1.f / fmaxf(sqrtf(n2), 1e-12f);
#pragma unroll
            for (int jj = 0; jj < 8; jj++)
                *(uint32_t*)(sm + P1_KPH + t * RSB + (c0 + 2 * jj) * 2) =
                    pack2(xk[2 * jj] * inv, xk[2 * jj + 1] * inv);
            ln16(xv, GB, c0);
#pragma unroll
            for (int jj = 0; jj < 8; jj++) {
                uint32_t hi, lo;
                packhl2(xv[2 * jj], xv[2 * jj + 1], hi, lo);
                *(uint32_t*)(sm + P1_VTH + t * RSB + (c0 + 2 * jj) * 2) = hi;
                *(uint32_t*)(sm + P1_VTL + t * RSB + (c0 + 2 * jj) * 2) = lo;
            }
        }
        __syncthreads();

        // ---- B: GEMM1 single-bf16: D1[t][m] = KN @ PJ^T ----
        float acc[4][4];
#pragma unroll
        for (int f = 0; f < 4; f++)
#pragma unroll
            for (int j = 0; j < 4; j++) acc[f][j] = 0.f;
#pragma unroll
        for (int ks = 0; ks < 4; ks++) {
            uint32_t Ah[4];
            ldsm4(Ah, aG1 + ks * 32);
#pragma unroll
            for (int f2 = 0; f2 < 2; f2++) {
                uint32_t Bh[4];
                ldsm4(Bh, bG1 + f2 * 16 * RSB + ks * 32);
                mma_bf16(acc[f2 * 2],     Ah, Bh[0], Bh[1]);
                mma_bf16(acc[f2 * 2 + 1], Ah, Bh[2], Bh[3]);
            }
        }
        __syncthreads();   // all reads of KN done (kp overlays)

        // ---- C: kp = featexp(D1) -> g_kp + hi/lo planes ----
        {
            uint32_t* gkp = g_kp + ((size_t)bh * TV + t0) * 32;
#pragma unroll
            for (int f = 0; f < 4; f++) {
                float x0 = featexp(acc[f][0]), x1 = featexp(acc[f][1]);
                float x2 = featexp(acc[f][2]), x3 = featexp(acc[f][3]);
                int c = nh * 32 + f * 8 + qk;
                gkp[tr * 32 + (c >> 1)] = pack2(x0, x1);
                gkp[(tr + 8) * 32 + (c >> 1)] = pack2(x2, x3);
                uint32_t hi, lo;
                packhl2(x0, x1, hi, lo);
                *(uint32_t*)(sm + P1_KPH + tr * RSB + c * 2) = hi;
                *(uint32_t*)(sm + P1_KPL + tr * RSB + c * 2) = lo;
                packhl2(x2, x3, hi, lo);
                *(uint32_t*)(sm + P1_KPH + (tr + 8) * RSB + c * 2) = hi;
                *(uint32_t*)(sm + P1_KPL + (tr + 8) * RSB + c * 2) = lo;
            }
        }
        __syncthreads();

        // ---- D: GEMM2 3-term: acc2[m][n] += kp^T @ vn ----
#pragma unroll
        for (int ks = 0; ks < 4; ks++) {
            uint32_t Ah[4], Al[4];
            ldsm4t(Ah, aG2 + ks * 16 * RSB);
            ldsm4t(Al, aG2 + PL + ks * 16 * RSB);
#pragma unroll
            for (int f2 = 0; f2 < 2; f2++) {
                uint32_t Bh[4], Bl[4];
                ldsm4t(Bh, bG2 + f2 * 32 + ks * 16 * RSB);
                ldsm4t(Bl, bG2 + PL + f2 * 32 + ks * 16 * RSB);
                mma3(acc2[f2 * 2],     Ah, Al, Bh[0], Bh[1], Bl[0], Bl[1]);
                mma3(acc2[f2 * 2 + 1], Ah, Al, Bh[2], Bh[3], Bl[2], Bl[3]);
            }
        }
        __syncthreads();
    }

    float* gp = g_part + (size_t)(bh * 16 + bx) * 4096;
#pragma unroll
    for (int f = 0; f < 4; f++) {
        int n = nh * 32 + f * 8 + qk;
        *(float2*)(gp + tr * 64 + n) = make_float2(acc2[f][0], acc2[f][1]);
        *(float2*)(gp + (tr + 8) * 64 + n) = make_float2(acc2[f][2], acc2[f][3]);
    }
}

// ---------------------------------------------------------------------------
extern "C" __global__ void __launch_bounds__(256) fa_reduce()
{
    const int tid = blockIdx.x * 256 + threadIdx.x;
    const int bh = tid >> 10, e4 = tid & 1023;
    const float4* p = (const float4*)(g_part + (size_t)bh * 16 * 4096) + e4;
    float4 s = make_float4(0.f, 0.f, 0.f, 0.f);
#pragma unroll
    for (int c = 0; c < 16; ++c) {
        float4 a = p[(size_t)c * 1024];
        s.x += a.x; s.y += a.y; s.z += a.z; s.w += a.w;
    }
    s.x *= 0.1f; s.y *= 0.1f; s.z *= 0.1f; s.w *= 0.1f;
    const int m = e4 >> 4, n0 = (e4 & 15) * 4;
    const int base = bh * 2304 + m * 36 + (n0 >> 1);
    uint32_t hi, lo;
    packhl2(s.x, s.y, hi, lo);
    g_kvh[base] = hi; g_kvl[base] = lo;
    packhl2(s.z, s.w, hi, lo);
    g_kvh[base + 1] = hi; g_kvl[base + 1] = lo;
}

// ---------------------------------------------------------------------------
// Pass 2: R6 structure; epilogue4 rebuilt as partial-stat exchange + register
// LayerNorm + direct gmem store (removes 32KB/tile smem traffic + 1 sync).
// ---------------------------------------------------------------------------
extern "C" __global__ void __launch_bounds__(256, 4) fa_pass2(
    const float* __restrict__ q, const float* __restrict__ gamma,
    const float* __restrict__ beta, float* __restrict__ out)
{
    extern __shared__ char sm[];
    const uint32_t sb = smem_u32(sm);
    float*  DEN = (float*)(sm + P2_DEN);
    float2* PD  = (float2*)(sm + P2_PD);
    float*  GB  = (float*)(sm + P2_GB);

    const int tid = threadIdx.x, lane = tid & 31, wid = tid >> 5;
    const int bh = blockIdx.y, bx = blockIdx.x;
    const int t = tid >> 2, c0 = (tid & 3) * 16;

    if (tid < 64) GB[tid] = gamma[tid];
    else if (tid < 128) GB[tid] = beta[tid - 64];
    {
        const uint4* src = (const uint4*)g_pjh;
        uint4* dst = (uint4*)(sm + P2_PJ);
        for (int i = tid; i < 576; i += 256) dst[i] = src[i];
        const uint4* kh = (const uint4*)(g_kvh + bh * 2304);
        const uint4* kl = (const uint4*)(g_kvl + bh * 2304);
        uint4* dh = (uint4*)(sm + P2_KVH);
        uint4* dl = (uint4*)(sm + P2_KVL);
        for (int i = tid; i < 576; i += 256) { dh[i] = kh[i]; dl[i] = kl[i]; }
    }
    __syncthreads();

    const int r = lane >> 2, qk = (lane & 3) * 2;
    const int mb = wid & 3, nh = wid >> 2;
    const int tr = mb * 16 + r;
    const int l7 = lane & 7, l8 = (lane >> 3) & 1, l16 = (lane >> 4) & 1;

    const uint32_t aG3 = sb + P2_QNH + (mb * 16 + l7 + l8 * 8) * RSB + l16 * 16;
    const uint32_t bG3 = sb + P2_PJ + (nh * 32 + l7 + l16 * 8) * RSB + l8 * 16;
    const uint32_t bG4 = sb + P2_KVH + (l7 + l8 * 8) * RSB + (nh * 32 + l16 * 8) * 2;

    for (int it = 0; it < TPC; ++it) {
        const int t0 = (bx * TPC + it) * 64;
        float x[16];

        // ---- LN + L2 of q -> QN (single bf16 plane) ----
        {
            const float* qr = q + ((size_t)(bh * TV + t0 + t)) * 64 + c0;
#pragma unroll
            for (int i = 0; i < 4; i++) *(float4*)(x + 4 * i) = *(const float4*)(qr + 4 * i);
            ln16(x, GB, c0);
            float n2 = 0.f;
#pragma unroll
            for (int j = 0; j < 16; j++) n2 += x[j] * x[j];
            n2 = qred(n2);
            float inv = 1.f / fmaxf(sqrtf(n2), 1e-12f);
#pragma unroll
            for (int jj = 0; jj < 8; jj++)
                *(uint32_t*)(sm + P2_QNH + t * RSB + (c0 + 2 * jj) * 2) =
                    pack2(x[2 * jj] * inv, x[2 * jj + 1] * inv);
        }
        __syncthreads();

        // ---- GEMM3 single-bf16: D3[t][m] = QN @ PJ^T ----
        float acc[4][4];
#pragma unroll
        for (int f = 0; f < 4; f++)
#pragma unroll
            for (int j = 0; j < 4; j++) acc[f][j] = 0.f;
#pragma unroll
        for (int ks = 0; ks < 4; ks++) {
            uint32_t Ah[4];
            ldsm4(Ah, aG3 + ks * 32);
#pragma unroll
            for (int f2 = 0; f2 < 2; f2++) {
                uint32_t Bh[4];
                ldsm4(Bh, bG3 + f2 * 16 * RSB + ks * 32);
                mma_bf16(acc[f2 * 2],     Ah, Bh[0], Bh[1]);
                mma_bf16(acc[f2 * 2 + 1], Ah, Bh[2], Bh[3]);
            }
        }
        __syncthreads();   // QN reads done (qp overlays)

        // ---- qp = featexp(D3) -> planes; denom partials vs g_kp ----
        {
            const uint32_t* gkp = g_kp + ((size_t)bh * TV + t0) * 32;
            float den0 = 0.f, den1 = 0.f;
#pragma unroll
            for (int f = 0; f < 4; f++) {
                float x0 = featexp(acc[f][0]), x1 = featexp(acc[f][1]);
                float x2 = featexp(acc[f][2]), x3 = featexp(acc[f][3]);
                int c = nh * 32 + f * 8 + qk;
                uint32_t hi, lo;
                packhl2(x0, x1, hi, lo);
                *(uint32_t*)(sm + P2_QNH + tr * RSB + c * 2) = hi;
                *(uint32_t*)(sm + P2_QPL + tr * RSB + c * 2) = lo;
                packhl2(x2, x3, hi, lo);
                *(uint32_t*)(sm + P2_QNH + (tr + 8) * RSB + c * 2) = hi;
                *(uint32_t*)(sm + P2_QPL + (tr + 8) * RSB + c * 2) = lo;
                float2 k0 = unpk2(gkp[tr * 32 + (c >> 1)]);
                float2 k1 = unpk2(gkp[(tr + 8) * 32 + (c >> 1)]);
                den0 += x0 * k0.x + x1 * k0.y;
                den1 += x2 * k1.x + x3 * k1.y;
            }
            den0 = qred(den0);
            den1 = qred(den1);
            if ((lane & 3) == 0) { DEN[nh * 64 + tr] = den0; DEN[nh * 64 + tr + 8] = den1; }
        }
        __syncthreads();

        // ---- GEMM4 3-term: D4[t][n] = qp @ kv ----
        float acc2[4][4];
#pragma unroll
        for (int f = 0; f < 4; f++)
#pragma unroll
            for (int j = 0; j < 4; j++) acc2[f][j] = 0.f;
#pragma unroll
        for (int ks = 0; ks < 4; ks++) {
            uint32_t Ah[4], Al[4];
            ldsm4(Ah, aG3 + ks * 32);
            ldsm4(Al, aG3 + PL + ks * 32);
#pragma unroll
            for (int f2 = 0; f2 < 2; f2++) {
                uint32_t Bh[4], Bl[4];
                ldsm4t(Bh, bG4 + f2 * 32 + ks * 16 * RSB);
                ldsm4t(Bl, bG4 + PL + f2 * 32 + ks * 16 * RSB);
                mma3(acc2[f2 * 2],     Ah, Al, Bh[0], Bh[1], Bl[0], Bl[1]);
                mma3(acc2[f2 * 2 + 1], Ah, Al, Bh[2], Bh[3], Bl[2], Bl[3]);
            }
        }

        // ---- epilogue4: scale by 0.1/den; partial row stats -> PD ----
        {
            float s0 = 0.1f / fmaxf(DEN[tr] + DEN[64 + tr], DEN_EPS);
            float s1 = 0.1f / fmaxf(DEN[tr + 8] + DEN[64 + tr + 8], DEN_EPS);
            float sA = 0.f, ssA = 0.f, sB = 0.f, ssB = 0.f;
#pragma unroll
            for (int f = 0; f < 4; f++) {
                acc2[f][0] *= s0; acc2[f][1] *= s0;
                acc2[f][2] *= s1; acc2[f][3] *= s1;
                sA += acc2[f][0] + acc2[f][1];
                ssA += acc2[f][0] * acc2[f][0] + acc2[f][1] * acc2[f][1];
                sB += acc2[f][2] + acc2[f][3];
                ssB += acc2[f][2] * acc2[f][2] + acc2[f][3] * acc2[f][3];
            }
            sA = qred(sA); ssA = qred(ssA);
            sB = qred(sB); ssB = qred(ssB);
            if ((lane & 3) == 0) {
                PD[nh * 128 + tr] = make_float2(sA, ssA);
                PD[nh * 128 + tr + 8] = make_float2(sB, ssB);
            }
        }
        __syncthreads();

        // ---- final LN from registers; direct gmem store ----
        {
            float2 a0 = PD[tr],     b0 = PD[128 + tr];
            float2 a1 = PD[tr + 8], b1 = PD[128 + tr + 8];
            float muA = (a0.x + b0.x) * (1.f / 64.f);
            float rsdA = rsqrtf((a0.y + b0.y) * (1.f / 64.f) - muA * muA + LN_EPS);
            float muB = (a1.x + b1.x) * (1.f / 64.f);
            float rsdB = rsqrtf((a1.y + b1.y) * (1.f / 64.f) - muB * muB + LN_EPS);
            float* o0 = out + ((size_t)(bh * TV + t0 + tr)) * 64;
            float* o1 = out + ((size_t)(bh * TV + t0 + tr + 8)) * 64;
#pragma unroll
            for (int f = 0; f < 4; f++) {
                int c = nh * 32 + f * 8 + qk;
                float g0 = GB[c], g1 = GB[c + 1];
                float be0 = GB[64 + c], be1 = GB[64 + c + 1];
                *(float2*)(o0 + c) = make_float2((acc2[f][0] - muA) * rsdA * g0 + be0,
                                                 (acc2[f][1] - muA) * rsdA * g1 + be1);
                *(float2*)(o1 + c) = make_float2((acc2[f][2] - muB) * rsdB * g0 + be0,
                                                 (acc2[f][3] - muB) * rsdB * g1 + be1);
            }
        }
    }
}

// ---------------------------------------------------------------------------
extern "C" void kernel_launch(void* const* d_in, const int* in_sizes, int n_in,
                              void* d_out, int out_size)
{
    const float* q     = (const float*)d_in[0];
    const float* k     = (const float*)d_in[1];
    const float* v     = (const float*)d_in[2];
    const float* proj  = (const float*)d_in[3];
    const float* gamma = (const float*)d_in[4];
    const float* beta  = (const float*)d_in[5];
    float* out = (float*)d_out;

    cudaFuncSetAttribute(fa_pass1, cudaFuncAttributeMaxDynamicSharedMemorySize, P1_BYTES);
    cudaFuncSetAttribute(fa_pass2, cudaFuncAttributeMaxDynamicSharedMemorySize, P2_BYTES);

    fa_setup<<<1, 256>>>(proj);
    fa_pass1<<<dim3(16, BHV), 256, P1_BYTES>>>(k, v, gamma, beta);
    fa_reduce<<<128, 256>>>();
    fa_pass2<<<dim3(16, BHV), 256, P2_BYTES>>>(q, gamma, beta, out);
}

// round 10
// speedup vs baseline: 2.5603x; 1.1113x over previous
#include <cuda_runtime.h>
#include <cuda_bf16.h>
#include <cstdint>

#define TV 8192
#define BHV 32
#define LN_EPS 1e-5f
#define DEN_EPS 1e-6f
#define RSB 144     // plane row stride bytes (72 bf16)
#define PL  9216    // hi->lo plane delta, bytes
#define TPC 8       // 64-token tiles per CTA

// Scratch (allocation-free)
__device__ uint32_t g_kp[(size_t)BHV * TV * 32];            // 32 MB kp 2xbf16 [bh][t][m/2]
__device__ float    g_part[(size_t)BHV * 16 * 4096];        // 8 MB partial kv
__device__ __align__(16) uint32_t g_pjh[2304];              // packed proj plane [m][n]
__device__ __align__(16) uint32_t g_kvh[(size_t)BHV * 2304];
__device__ __align__(16) uint32_t g_kvl[(size_t)BHV * 2304];

// ---------------- helpers ----------------
__device__ __forceinline__ uint32_t smem_u32(const void* p) {
    uint32_t a;
    asm("{ .reg .u64 t; cvta.to.shared.u64 t, %1; cvt.u32.u64 %0, t; }" : "=r"(a) : "l"(p));
    return a;
}
__device__ __forceinline__ float featexp(float x) {
    return __expf(fminf(fmaxf(x, -15.f), 15.f)) * 0.1f;
}
__device__ __forceinline__ float qred(float v) {
    v += __shfl_xor_sync(0xffffffffu, v, 1);
    v += __shfl_xor_sync(0xffffffffu, v, 2);
    return v;
}
__device__ __forceinline__ uint32_t pack2(float x, float y) {
    __nv_bfloat162 b = __floats2bfloat162_rn(x, y);
    return *(uint32_t*)&b;
}
__device__ __forceinline__ float2 unpk2(uint32_t p) {
    __nv_bfloat162 b = *(__nv_bfloat162*)&p;
    return make_float2(__bfloat162float(b.x), __bfloat162float(b.y));
}
__device__ __forceinline__ void packhl2(float a, float b, uint32_t& hi, uint32_t& lo) {
    __nv_bfloat16 ha = __float2bfloat16_rn(a), hb = __float2bfloat16_rn(b);
    __nv_bfloat16 la = __float2bfloat16_rn(a - __bfloat162float(ha));
    __nv_bfloat16 lb = __float2bfloat16_rn(b - __bfloat162float(hb));
    hi = (uint32_t)__bfloat16_as_ushort(ha) | ((uint32_t)__bfloat16_as_ushort(hb) << 16);
    lo = (uint32_t)__bfloat16_as_ushort(la) | ((uint32_t)__bfloat16_as_ushort(lb) << 16);
}
__device__ __forceinline__ void ldsm4(uint32_t* r, uint32_t a) {
    asm volatile("ldmatrix.sync.aligned.m8n8.x4.shared.b16 {%0,%1,%2,%3}, [%4];"
        : "=r"(r[0]), "=r"(r[1]), "=r"(r[2]), "=r"(r[3]) : "r"(a));
}
__device__ __forceinline__ void ldsm4t(uint32_t* r, uint32_t a) {
    asm volatile("ldmatrix.sync.aligned.m8n8.x4.trans.shared.b16 {%0,%1,%2,%3}, [%4];"
        : "=r"(r[0]), "=r"(r[1]), "=r"(r[2]), "=r"(r[3]) : "r"(a));
}
__device__ __forceinline__ void mma_bf16(float* c, const uint32_t* a, uint32_t b0, uint32_t b1) {
    asm("mma.sync.aligned.m16n8k16.row.col.f32.bf16.bf16.f32 "
        "{%0,%1,%2,%3},{%4,%5,%6,%7},{%8,%9},{%0,%1,%2,%3};"
        : "+f"(c[0]), "+f"(c[1]), "+f"(c[2]), "+f"(c[3])
        : "r"(a[0]), "r"(a[1]), "r"(a[2]), "r"(a[3]), "r"(b0), "r"(b1));
}
__device__ __forceinline__ void mma3(float* c, const uint32_t* Ah, const uint32_t* Al,
                                     uint32_t bh0, uint32_t bh1, uint32_t bl0, uint32_t bl1) {
    mma_bf16(c, Ah, bh0, bh1);
    mma_bf16(c, Ah, bl0, bl1);
    mma_bf16(c, Al, bh0, bh1);
}
__device__ __forceinline__ void ln16(float* x, const float* GB, int c0) {
    float s = 0.f, ss = 0.f;
#pragma unroll
    for (int j = 0; j < 16; j++) { s += x[j]; ss += x[j] * x[j]; }
    s = qred(s); ss = qred(ss);
    float mu = s * (1.f / 64.f);
    float rstd = rsqrtf(ss * (1.f / 64.f) - mu * mu + LN_EPS);
#pragma unroll
    for (int j = 0; j < 16; j++)
        x[j] = (x[j] - mu) * rstd * GB[c0 + j] + GB[64 + c0 + j];
}

// pass1 byte offsets (KN separate; 2 syncs per tile)
#define P1_KN  0
#define P1_KPH 9216
#define P1_KPL 18432    // = KPH + PL
#define P1_PJ  27648
#define P1_VTH 36864
#define P1_VTL 46080    // = VTH + PL
#define P1_GB  55296
#define P1_BYTES 55808
// pass2 byte offsets (EXACT R9)
#define P2_QNH 0       // QN single plane, overlaid by qp-hi
#define P2_QPL 9216    // qp-lo
#define P2_PJ  18432
#define P2_KVH 27648
#define P2_KVL 36864
#define P2_DEN 46080
#define P2_PD  46592   // 256 x float2
#define P2_GB  48640
#define P2_BYTES 49152

// ---------------------------------------------------------------------------
extern "C" __global__ void fa_setup(const float* __restrict__ proj)
{
    const int tid = threadIdx.x;
    for (int i = tid; i < 2048; i += 256) {
        int m = i & 63, nw = i >> 6;
        g_pjh[m * 36 + nw] = pack2(proj[(2 * nw) * 64 + m], proj[(2 * nw + 1) * 64 + m]);
    }
}

// ---------------------------------------------------------------------------
// Pass 1: CTA = 512 tokens, 8 x 64-token tiles, TWO syncs per tile.
// Phases: LNk -> S1 -> GEMM1 -> epi(kp) -> LNv -> S2 -> GEMM2.
// Cross-warp W/R audit:
//   LNk(i+1) W[KN]  vs G2(i) R[KP,VT]     : disjoint planes
//   epi(i)   W[KP]  vs G1(i) R[KN,PJ]     : disjoint planes
//   epi(i+1) W[KP]  vs G2(i) R[KP]        : separated by S1(i+1)
//   LNv(i+1) W[VT]  vs G2(i) R[VT]        : separated by S1(i+1)
//   LNk(i)   W[KN]  vs G1(i) R[KN]        : separated by S1(i)
//   epi/LNv(i) W[KP,VT] vs G2(i) R[KP,VT] : separated by S2(i)
// ---------------------------------------------------------------------------
extern "C" __global__ void __launch_bounds__(256, 4) fa_pass1(
    const float* __restrict__ k, const float* __restrict__ v,
    const float* __restrict__ gamma, const float* __restrict__ beta)
{
    extern __shared__ char sm[];
    const uint32_t sb = smem_u32(sm);
    float* GB = (float*)(sm + P1_GB);

    const int tid = threadIdx.x, lane = tid & 31, wid = tid >> 5;
    const int bh = blockIdx.y, bx = blockIdx.x;
    const int t = tid >> 2, c0 = (tid & 3) * 16;

    if (tid < 64) GB[tid] = gamma[tid];
    else if (tid < 128) GB[tid] = beta[tid - 64];
    {
        const uint4* src = (const uint4*)g_pjh;
        uint4* dst = (uint4*)(sm + P1_PJ);
        for (int i = tid; i < 576; i += 256) dst[i] = src[i];
    }
    __syncthreads();

    const int r = lane >> 2, qk = (lane & 3) * 2;
    const int mb = wid & 3, nh = wid >> 2;
    const int tr = mb * 16 + r;
    const int l7 = lane & 7, l8 = (lane >> 3) & 1, l16 = (lane >> 4) & 1;

    const uint32_t aG1 = sb + P1_KN + (mb * 16 + l7 + l8 * 8) * RSB + l16 * 16;
    const uint32_t bG1 = sb + P1_PJ + (nh * 32 + l7 + l16 * 8) * RSB + l8 * 16;
    const uint32_t aG2 = sb + P1_KPH + (l7 + l16 * 8) * RSB + (mb * 16 + l8 * 8) * 2;
    const uint32_t bG2 = sb + P1_VTH + (l7 + l8 * 8) * RSB + (nh * 32 + l16 * 8) * 2;

    float acc2[4][4];
#pragma unroll
    for (int f = 0; f < 4; f++)
#pragma unroll
        for (int j = 0; j < 4; j++) acc2[f][j] = 0.f;

    for (int it = 0; it < TPC; ++it) {
        const int t0 = (bx * TPC + it) * 64;
        const float* kr = k + ((size_t)(bh * TV + t0 + t)) * 64 + c0;
        const float* vr = v + ((size_t)(bh * TV + t0 + t)) * 64 + c0;

        // ---- Phase 1: LN(k)+L2 -> KN (single bf16); L2-prefetch v ----
        {
            asm volatile("prefetch.global.L2 [%0];" :: "l"(vr));
            float xk[16];
#pragma unroll
            for (int i = 0; i < 4; i++) *(float4*)(xk + 4 * i) = *(const float4*)(kr + 4 * i);
            ln16(xk, GB, c0);
            float n2 = 0.f;
#pragma unroll
            for (int j = 0; j < 16; j++) n2 += xk[j] * xk[j];
            n2 = qred(n2);
            float inv = 1.f / fmaxf(sqrtf(n2), 1e-12f);
#pragma unroll
            for (int jj = 0; jj < 8; jj++)
                *(uint32_t*)(sm + P1_KN + t * RSB + (c0 + 2 * jj) * 2) =
                    pack2(xk[2 * jj] * inv, xk[2 * jj + 1] * inv);
        }
        __syncthreads();   // S1

        // ---- Phase 2: GEMM1 single-bf16: D1[t][m] = KN @ PJ^T ----
        float acc[4][4];
#pragma unroll
        for (int f = 0; f < 4; f++)
#pragma unroll
            for (int j = 0; j < 4; j++) acc[f][j] = 0.f;
#pragma unroll
        for (int ks = 0; ks < 4; ks++) {
            uint32_t Ah[4];
            ldsm4(Ah, aG1 + ks * 32);
#pragma unroll
            for (int f2 = 0; f2 < 2; f2++) {
                uint32_t Bh[4];
                ldsm4(Bh, bG1 + f2 * 16 * RSB + ks * 32);
                mma_bf16(acc[f2 * 2],     Ah, Bh[0], Bh[1]);
                mma_bf16(acc[f2 * 2 + 1], Ah, Bh[2], Bh[3]);
            }
        }

        // ---- Phase 3: kp = featexp(D1) -> g_kp + KP hi/lo planes ----
        {
            uint32_t* gkp = g_kp + ((size_t)bh * TV + t0) * 32;
#pragma unroll
            for (int f = 0; f < 4; f++) {
                float x0 = featexp(acc[f][0]), x1 = featexp(acc[f][1]);
                float x2 = featexp(acc[f][2]), x3 = featexp(acc[f][3]);
                int c = nh * 32 + f * 8 + qk;
                gkp[tr * 32 + (c >> 1)] = pack2(x0, x1);
                gkp[(tr + 8) * 32 + (c >> 1)] = pack2(x2, x3);
                uint32_t hi, lo;
                packhl2(x0, x1, hi, lo);
                *(uint32_t*)(sm + P1_KPH + tr * RSB + c * 2) = hi;
                *(uint32_t*)(sm + P1_KPL + tr * RSB + c * 2) = lo;
                packhl2(x2, x3, hi, lo);
                *(uint32_t*)(sm + P1_KPH + (tr + 8) * RSB + c * 2) = hi;
                *(uint32_t*)(sm + P1_KPL + (tr + 8) * RSB + c * 2) = lo;
            }
        }

        // ---- Phase 4: LN(v) -> VT hi/lo ----
        {
            float xv[16];
#pragma unroll
            for (int i = 0; i < 4; i++) *(float4*)(xv + 4 * i) = *(const float4*)(vr + 4 * i);
            ln16(xv, GB, c0);
#pragma unroll
            for (int jj = 0; jj < 8; jj++) {
                uint32_t hi, lo;
                packhl2(xv[2 * jj], xv[2 * jj + 1], hi, lo);
                *(uint32_t*)(sm + P1_VTH + t * RSB + (c0 + 2 * jj) * 2) = hi;
                *(uint32_t*)(sm + P1_VTL + t * RSB + (c0 + 2 * jj) * 2) = lo;
            }
        }
        __syncthreads();   // S2

        // ---- Phase 5: GEMM2 3-term: acc2[m][n] += kp^T @ vn ----
#pragma unroll
        for (int ks = 0; ks < 4; ks++) {
            uint32_t Ah[4], Al[4];
            ldsm4t(Ah, aG2 + ks * 16 * RSB);
            ldsm4t(Al, aG2 + PL + ks * 16 * RSB);
#pragma unroll
            for (int f2 = 0; f2 < 2; f2++) {
                uint32_t Bh[4], Bl[4];
                ldsm4t(Bh, bG2 + f2 * 32 + ks * 16 * RSB);
                ldsm4t(Bl, bG2 + PL + f2 * 32 + ks * 16 * RSB);
                mma3(acc2[f2 * 2],     Ah, Al, Bh[0], Bh[1], Bl[0], Bl[1]);
                mma3(acc2[f2 * 2 + 1], Ah, Al, Bh[2], Bh[3], Bl[2], Bl[3]);
            }
        }
        // no loop-end sync: next LNk writes KN only; GEMM2 reads KP/VT
    }

    float* gp = g_part + (size_t)(bh * 16 + bx) * 4096;
#pragma unroll
    for (int f = 0; f < 4; f++) {
        int n = nh * 32 + f * 8 + qk;
        *(float2*)(gp + tr * 64 + n) = make_float2(acc2[f][0], acc2[f][1]);
        *(float2*)(gp + (tr + 8) * 64 + n) = make_float2(acc2[f][2], acc2[f][3]);
    }
}

// ---------------------------------------------------------------------------
extern "C" __global__ void __launch_bounds__(256) fa_reduce()
{
    const int tid = blockIdx.x * 256 + threadIdx.x;
    const int bh = tid >> 10, e4 = tid & 1023;
    const float4* p = (const float4*)(g_part + (size_t)bh * 16 * 4096) + e4;
    float4 s = make_float4(0.f, 0.f, 0.f, 0.f);
#pragma unroll
    for (int c = 0; c < 16; ++c) {
        float4 a = p[(size_t)c * 1024];
        s.x += a.x; s.y += a.y; s.z += a.z; s.w += a.w;
    }
    s.x *= 0.1f; s.y *= 0.1f; s.z *= 0.1f; s.w *= 0.1f;
    const int m = e4 >> 4, n0 = (e4 & 15) * 4;
    const int base = bh * 2304 + m * 36 + (n0 >> 1);
    uint32_t hi, lo;
    packhl2(s.x, s.y, hi, lo);
    g_kvh[base] = hi; g_kvl[base] = lo;
    packhl2(s.z, s.w, hi, lo);
    g_kvh[base + 1] = hi; g_kvl[base + 1] = lo;
}

// ---------------------------------------------------------------------------
// Pass 2: EXACT R9 (proven at 83.5us).
// ---------------------------------------------------------------------------
extern "C" __global__ void __launch_bounds__(256, 4) fa_pass2(
    const float* __restrict__ q, const float* __restrict__ gamma,
    const float* __restrict__ beta, float* __restrict__ out)
{
    extern __shared__ char sm[];
    const uint32_t sb = smem_u32(sm);
    float*  DEN = (float*)(sm + P2_DEN);
    float2* PD  = (float2*)(sm + P2_PD);
    float*  GB  = (float*)(sm + P2_GB);

    const int tid = threadIdx.x, lane = tid & 31, wid = tid >> 5;
    const int bh = blockIdx.y, bx = blockIdx.x;
    const int t = tid >> 2, c0 = (tid & 3) * 16;

    if (tid < 64) GB[tid] = gamma[tid];
    else if (tid < 128) GB[tid] = beta[tid - 64];
    {
        const uint4* src = (const uint4*)g_pjh;
        uint4* dst = (uint4*)(sm + P2_PJ);
        for (int i = tid; i < 576; i += 256) dst[i] = src[i];
        const uint4* kh = (const uint4*)(g_kvh + bh * 2304);
        const uint4* kl = (const uint4*)(g_kvl + bh * 2304);
        uint4* dh = (uint4*)(sm + P2_KVH);
        uint4* dl = (uint4*)(sm + P2_KVL);
        for (int i = tid; i < 576; i += 256) { dh[i] = kh[i]; dl[i] = kl[i]; }
    }
    __syncthreads();

    const int r = lane >> 2, qk = (lane & 3) * 2;
    const int mb = wid & 3, nh = wid >> 2;
    const int tr = mb * 16 + r;
    const int l7 = lane & 7, l8 = (lane >> 3) & 1, l16 = (lane >> 4) & 1;

    const uint32_t aG3 = sb + P2_QNH + (mb * 16 + l7 + l8 * 8) * RSB + l16 * 16;
    const uint32_t bG3 = sb + P2_PJ + (nh * 32 + l7 + l16 * 8) * RSB + l8 * 16;
    const uint32_t bG4 = sb + P2_KVH + (l7 + l8 * 8) * RSB + (nh * 32 + l16 * 8) * 2;

    for (int it = 0; it < TPC; ++it) {
        const int t0 = (bx * TPC + it) * 64;
        float x[16];

        // ---- LN + L2 of q -> QN (single bf16 plane) ----
        {
            const float* qr = q + ((size_t)(bh * TV + t0 + t)) * 64 + c0;
#pragma unroll
            for (int i = 0; i < 4; i++) *(float4*)(x + 4 * i) = *(const float4*)(qr + 4 * i);
            ln16(x, GB, c0);
            float n2 = 0.f;
#pragma unroll
            for (int j = 0; j < 16; j++) n2 += x[j] * x[j];
            n2 = qred(n2);
            float inv = 1.f / fmaxf(sqrtf(n2), 1e-12f);
#pragma unroll
            for (int jj = 0; jj < 8; jj++)
                *(uint32_t*)(sm + P2_QNH + t * RSB + (c0 + 2 * jj) * 2) =
                    pack2(x[2 * jj] * inv, x[2 * jj + 1] * inv);
        }
        __syncthreads();

        // ---- GEMM3 single-bf16: D3[t][m] = QN @ PJ^T ----
        float acc[4][4];
#pragma unroll
        for (int f = 0; f < 4; f++)
#pragma unroll
            for (int j = 0; j < 4; j++) acc[f][j] = 0.f;
#pragma unroll
        for (int ks = 0; ks < 4; ks++) {
            uint32_t Ah[4];
            ldsm4(Ah, aG3 + ks * 32);
#pragma unroll
            for (int f2 = 0; f2 < 2; f2++) {
                uint32_t Bh[4];
                ldsm4(Bh, bG3 + f2 * 16 * RSB + ks * 32);
                mma_bf16(acc[f2 * 2],     Ah, Bh[0], Bh[1]);
                mma_bf16(acc[f2 * 2 + 1], Ah, Bh[2], Bh[3]);
            }
        }
        __syncthreads();   // QN reads done (qp overlays)

        // ---- qp = featexp(D3) -> planes; denom partials vs g_kp ----
        {
            const uint32_t* gkp = g_kp + ((size_t)bh * TV + t0) * 32;
            float den0 = 0.f, den1 = 0.f;
#pragma unroll
            for (int f = 0; f < 4; f++) {
                float x0 = featexp(acc[f][0]), x1 = featexp(acc[f][1]);
                float x2 = featexp(acc[f][2]), x3 = featexp(acc[f][3]);
                int c = nh * 32 + f * 8 + qk;
                uint32_t hi, lo;
                packhl2(x0, x1, hi, lo);
                *(uint32_t*)(sm + P2_QNH + tr * RSB + c * 2) = hi;
                *(uint32_t*)(sm + P2_QPL + tr * RSB + c * 2) = lo;
                packhl2(x2, x3, hi, lo);
                *(uint32_t*)(sm + P2_QNH + (tr + 8) * RSB + c * 2) = hi;
                *(uint32_t*)(sm + P2_QPL + (tr + 8) * RSB + c * 2) = lo;
                float2 k0 = unpk2(gkp[tr * 32 + (c >> 1)]);
                float2 k1 = unpk2(gkp[(tr + 8) * 32 + (c >> 1)]);
                den0 += x0 * k0.x + x1 * k0.y;
                den1 += x2 * k1.x + x3 * k1.y;
            }
            den0 = qred(den0);
            den1 = qred(den1);
            if ((lane & 3) == 0) { DEN[nh * 64 + tr] = den0; DEN[nh * 64 + tr + 8] = den1; }
        }
        __syncthreads();

        // ---- GEMM4 3-term: D4[t][n] = qp @ kv ----
        float acc2[4][4];
#pragma unroll
        for (int f = 0; f < 4; f++)
#pragma unroll
            for (int j = 0; j < 4; j++) acc2[f][j] = 0.f;
#pragma unroll
        for (int ks = 0; ks < 4; ks++) {
            uint32_t Ah[4], Al[4];
            ldsm4(Ah, aG3 + ks * 32);
            ldsm4(Al, aG3 + PL + ks * 32);
#pragma unroll
            for (int f2 = 0; f2 < 2; f2++) {
                uint32_t Bh[4], Bl[4];
                ldsm4t(Bh, bG4 + f2 * 32 + ks * 16 * RSB);
                ldsm4t(Bl, bG4 + PL + f2 * 32 + ks * 16 * RSB);
                mma3(acc2[f2 * 2],     Ah, Al, Bh[0], Bh[1], Bl[0], Bl[1]);
                mma3(acc2[f2 * 2 + 1], Ah, Al, Bh[2], Bh[3], Bl[2], Bl[3]);
            }
        }

        // ---- epilogue4: scale by 0.1/den; partial row stats -> PD ----
        {
            float s0 = 0.1f / fmaxf(DEN[tr] + DEN[64 + tr], DEN_EPS);
            float s1 = 0.1f / fmaxf(DEN[tr + 8] + DEN[64 + tr + 8], DEN_EPS);
            float sA = 0.f, ssA = 0.f, sB = 0.f, ssB = 0.f;
#pragma unroll
            for (int f = 0; f < 4; f++) {
                acc2[f][0] *= s0; acc2[f][1] *= s0;
                acc2[f][2] *= s1; acc2[f][3] *= s1;
                sA += acc2[f][0] + acc2[f][1];
                ssA += acc2[f][0] * acc2[f][0] + acc2[f][1] * acc2[f][1];
                sB += acc2[f][2] + acc2[f][3];
                ssB += acc2[f][2] * acc2[f][2] + acc2[f][3] * acc2[f][3];
            }
            sA = qred(sA); ssA = qred(ssA);
            sB = qred(sB); ssB = qred(ssB);
            if ((lane & 3) == 0) {
                PD[nh * 128 + tr] = make_float2(sA, ssA);
                PD[nh * 128 + tr + 8] = make_float2(sB, ssB);
            }
        }
        __syncthreads();

        // ---- final LN from registers; direct gmem store ----
        {
            float2 a0 = PD[tr],     b0 = PD[128 + tr];
            float2 a1 = PD[tr + 8], b1 = PD[128 + tr + 8];
            float muA = (a0.x + b0.x) * (1.f / 64.f);
            float rsdA = rsqrtf((a0.y + b0.y) * (1.f / 64.f) - muA * muA + LN_EPS);
            float muB = (a1.x + b1.x) * (1.f / 64.f);
            float rsdB = rsqrtf((a1.y + b1.y) * (1.f / 64.f) - muB * muB + LN_EPS);
            float* o0 = out + ((size_t)(bh * TV + t0 + tr)) * 64;
            float* o1 = out + ((size_t)(bh * TV + t0 + tr + 8)) * 64;
#pragma unroll
            for (int f = 0; f < 4; f++) {
                int c = nh * 32 + f * 8 + qk;
                float g0 = GB[c], g1 = GB[c + 1];
                float be0 = GB[64 + c], be1 = GB[64 + c + 1];
                *(float2*)(o0 + c) = make_float2((acc2[f][0] - muA) * rsdA * g0 + be0,
                                                 (acc2[f][1] - muA) * rsdA * g1 + be1);
                *(float2*)(o1 + c) = make_float2((acc2[f][2] - muB) * rsdB * g0 + be0,
                                                 (acc2[f][3] - muB) * rsdB * g1 + be1);
            }
        }
    }
}

// ---------------------------------------------------------------------------
extern "C" void kernel_launch(void* const* d_in, const int* in_sizes, int n_in,
                              void* d_out, int out_size)
{
    const float* q     = (const float*)d_in[0];
    const float* k     = (const float*)d_in[1];
    const float* v     = (const float*)d_in[2];
    const float* proj  = (const float*)d_in[3];
    const float* gamma = (const float*)d_in[4];
    const float* beta  = (const float*)d_in[5];
    float* out = (float*)d_out;

    cudaFuncSetAttribute(fa_pass1, cudaFuncAttributeMaxDynamicSharedMemorySize, P1_BYTES);
    cudaFuncSetAttribute(fa_pass2, cudaFuncAttributeMaxDynamicSharedMemorySize, P2_BYTES);

    fa_setup<<<1, 256>>>(proj);
    fa_pass1<<<dim3(16, BHV), 256, P1_BYTES>>>(k, v, gamma, beta);
    fa_reduce<<<128, 256>>>();
    fa_pass2<<<dim3(16, BHV), 256, P2_BYTES>>>(q, gamma, beta, out);
}

// round 11
// speedup vs baseline: 2.5944x; 1.0133x over previous
#include <cuda_runtime.h>
#include <cuda_bf16.h>
#include <cstdint>

#define TV 8192
#define BHV 32
#define LN_EPS 1e-5f
#define DEN_EPS 1e-6f
#define RSB 144     // plane row stride bytes (72 bf16)
#define PL  9216    // hi->lo plane delta, bytes
#define TPC 8       // 64-token tiles per CTA

// Scratch (allocation-free)
__device__ uint32_t g_kp[(size_t)BHV * TV * 32];            // 32 MB kp 2xbf16 [bh][t][m/2]
__device__ float    g_part[(size_t)BHV * 16 * 4096];        // 8 MB partial kv
__device__ __align__(16) uint32_t g_pjh[2304];              // packed proj plane [m][n]
__device__ __align__(16) uint32_t g_kvh[(size_t)BHV * 2304];
__device__ __align__(16) uint32_t g_kvl[(size_t)BHV * 2304];

// ---------------- helpers ----------------
__device__ __forceinline__ uint32_t smem_u32(const void* p) {
    uint32_t a;
    asm("{ .reg .u64 t; cvta.to.shared.u64 t, %1; cvt.u32.u64 %0, t; }" : "=r"(a) : "l"(p));
    return a;
}
__device__ __forceinline__ float featexp(float x) {
    return __expf(fminf(fmaxf(x, -15.f), 15.f)) * 0.1f;
}
__device__ __forceinline__ float qred(float v) {
    v += __shfl_xor_sync(0xffffffffu, v, 1);
    v += __shfl_xor_sync(0xffffffffu, v, 2);
    return v;
}
__device__ __forceinline__ uint32_t pack2(float x, float y) {
    __nv_bfloat162 b = __floats2bfloat162_rn(x, y);
    return *(uint32_t*)&b;
}
__device__ __forceinline__ float2 unpk2(uint32_t p) {
    __nv_bfloat162 b = *(__nv_bfloat162*)&p;
    return make_float2(__bfloat162float(b.x), __bfloat162float(b.y));
}
__device__ __forceinline__ void packhl2(float a, float b, uint32_t& hi, uint32_t& lo) {
    __nv_bfloat16 ha = __float2bfloat16_rn(a), hb = __float2bfloat16_rn(b);
    __nv_bfloat16 la = __float2bfloat16_rn(a - __bfloat162float(ha));
    __nv_bfloat16 lb = __float2bfloat16_rn(b - __bfloat162float(hb));
    hi = (uint32_t)__bfloat16_as_ushort(ha) | ((uint32_t)__bfloat16_as_ushort(hb) << 16);
    lo = (uint32_t)__bfloat16_as_ushort(la) | ((uint32_t)__bfloat16_as_ushort(lb) << 16);
}
__device__ __forceinline__ void ldsm4(uint32_t* r, uint32_t a) {
    asm volatile("ldmatrix.sync.aligned.m8n8.x4.shared.b16 {%0,%1,%2,%3}, [%4];"
        : "=r"(r[0]), "=r"(r[1]), "=r"(r[2]), "=r"(r[3]) : "r"(a));
}
__device__ __forceinline__ void ldsm4t(uint32_t* r, uint32_t a) {
    asm volatile("ldmatrix.sync.aligned.m8n8.x4.trans.shared.b16 {%0,%1,%2,%3}, [%4];"
        : "=r"(r[0]), "=r"(r[1]), "=r"(r[2]), "=r"(r[3]) : "r"(a));
}
__device__ __forceinline__ void mma_bf16(float* c, const uint32_t* a, uint32_t b0, uint32_t b1) {
    asm("mma.sync.aligned.m16n8k16.row.col.f32.bf16.bf16.f32 "
        "{%0,%1,%2,%3},{%4,%5,%6,%7},{%8,%9},{%0,%1,%2,%3};"
        : "+f"(c[0]), "+f"(c[1]), "+f"(c[2]), "+f"(c[3])
        : "r"(a[0]), "r"(a[1]), "r"(a[2]), "r"(a[3]), "r"(b0), "r"(b1));
}
__device__ __forceinline__ void mma3(float* c, const uint32_t* Ah, const uint32_t* Al,
                                     uint32_t bh0, uint32_t bh1, uint32_t bl0, uint32_t bl1) {
    mma_bf16(c, Ah, bh0, bh1);
    mma_bf16(c, Ah, bl0, bl1);
    mma_bf16(c, Al, bh0, bh1);
}
__device__ __forceinline__ void ln16(float* x, const float* GB, int c0) {
    float s = 0.f, ss = 0.f;
#pragma unroll
    for (int j = 0; j < 16; j++) { s += x[j]; ss += x[j] * x[j]; }
    s = qred(s); ss = qred(ss);
    float mu = s * (1.f / 64.f);
    float rstd = rsqrtf(ss * (1.f / 64.f) - mu * mu + LN_EPS);
#pragma unroll
    for (int j = 0; j < 16; j++)
        x[j] = (x[j] - mu) * rstd * GB[c0 + j] + GB[64 + c0 + j];
}

// pass1 byte offsets (EXACT R10)
#define P1_KN  0
#define P1_KPH 9216
#define P1_KPL 18432
#define P1_PJ  27648
#define P1_VTH 36864
#define P1_VTL 46080
#define P1_GB  55296
#define P1_BYTES 55808
// pass2 byte offsets (EXACT R9/R10)
#define P2_QNH 0       // QN single plane, overlaid by qp-hi
#define P2_QPL 9216    // qp-lo
#define P2_PJ  18432
#define P2_KVH 27648
#define P2_KVL 36864
#define P2_DEN 46080
#define P2_PD  46592   // 256 x float2
#define P2_GB  48640
#define P2_BYTES 49152

// ---------------------------------------------------------------------------
extern "C" __global__ void fa_setup(const float* __restrict__ proj)
{
    const int tid = threadIdx.x;
    for (int i = tid; i < 2048; i += 256) {
        int m = i & 63, nw = i >> 6;
        g_pjh[m * 36 + nw] = pack2(proj[(2 * nw) * 64 + m], proj[(2 * nw + 1) * 64 + m]);
    }
}

// ---------------------------------------------------------------------------
// Pass 1: EXACT R10 (proven). CTA = 512 tokens, 2 syncs per tile.
// ---------------------------------------------------------------------------
extern "C" __global__ void __launch_bounds__(256, 4) fa_pass1(
    const float* __restrict__ k, const float* __restrict__ v,
    const float* __restrict__ gamma, const float* __restrict__ beta)
{
    extern __shared__ char sm[];
    const uint32_t sb = smem_u32(sm);
    float* GB = (float*)(sm + P1_GB);

    const int tid = threadIdx.x, lane = tid & 31, wid = tid >> 5;
    const int bh = blockIdx.y, bx = blockIdx.x;
    const int t = tid >> 2, c0 = (tid & 3) * 16;

    if (tid < 64) GB[tid] = gamma[tid];
    else if (tid < 128) GB[tid] = beta[tid - 64];
    {
        const uint4* src = (const uint4*)g_pjh;
        uint4* dst = (uint4*)(sm + P1_PJ);
        for (int i = tid; i < 576; i += 256) dst[i] = src[i];
    }
    __syncthreads();

    const int r = lane >> 2, qk = (lane & 3) * 2;
    const int mb = wid & 3, nh = wid >> 2;
    const int tr = mb * 16 + r;
    const int l7 = lane & 7, l8 = (lane >> 3) & 1, l16 = (lane >> 4) & 1;

    const uint32_t aG1 = sb + P1_KN + (mb * 16 + l7 + l8 * 8) * RSB + l16 * 16;
    const uint32_t bG1 = sb + P1_PJ + (nh * 32 + l7 + l16 * 8) * RSB + l8 * 16;
    const uint32_t aG2 = sb + P1_KPH + (l7 + l16 * 8) * RSB + (mb * 16 + l8 * 8) * 2;
    const uint32_t bG2 = sb + P1_VTH + (l7 + l8 * 8) * RSB + (nh * 32 + l16 * 8) * 2;

    float acc2[4][4];
#pragma unroll
    for (int f = 0; f < 4; f++)
#pragma unroll
        for (int j = 0; j < 4; j++) acc2[f][j] = 0.f;

    for (int it = 0; it < TPC; ++it) {
        const int t0 = (bx * TPC + it) * 64;
        const float* kr = k + ((size_t)(bh * TV + t0 + t)) * 64 + c0;
        const float* vr = v + ((size_t)(bh * TV + t0 + t)) * 64 + c0;

        // ---- Phase 1: LN(k)+L2 -> KN; L2-prefetch v ----
        {
            asm volatile("prefetch.global.L2 [%0];" :: "l"(vr));
            float xk[16];
#pragma unroll
            for (int i = 0; i < 4; i++) *(float4*)(xk + 4 * i) = *(const float4*)(kr + 4 * i);
            ln16(xk, GB, c0);
            float n2 = 0.f;
#pragma unroll
            for (int j = 0; j < 16; j++) n2 += xk[j] * xk[j];
            n2 = qred(n2);
            float inv = 1.f / fmaxf(sqrtf(n2), 1e-12f);
#pragma unroll
            for (int jj = 0; jj < 8; jj++)
                *(uint32_t*)(sm + P1_KN + t * RSB + (c0 + 2 * jj) * 2) =
                    pack2(xk[2 * jj] * inv, xk[2 * jj + 1] * inv);
        }
        __syncthreads();   // S1

        // ---- Phase 2: GEMM1 single-bf16 ----
        float acc[4][4];
#pragma unroll
        for (int f = 0; f < 4; f++)
#pragma unroll
            for (int j = 0; j < 4; j++) acc[f][j] = 0.f;
#pragma unroll
        for (int ks = 0; ks < 4; ks++) {
            uint32_t Ah[4];
            ldsm4(Ah, aG1 + ks * 32);
#pragma unroll
            for (int f2 = 0; f2 < 2; f2++) {
                uint32_t Bh[4];
                ldsm4(Bh, bG1 + f2 * 16 * RSB + ks * 32);
                mma_bf16(acc[f2 * 2],     Ah, Bh[0], Bh[1]);
                mma_bf16(acc[f2 * 2 + 1], Ah, Bh[2], Bh[3]);
            }
        }

        // ---- Phase 3: kp = featexp(D1) -> g_kp + KP hi/lo planes ----
        {
            uint32_t* gkp = g_kp + ((size_t)bh * TV + t0) * 32;
#pragma unroll
            for (int f = 0; f < 4; f++) {
                float x0 = featexp(acc[f][0]), x1 = featexp(acc[f][1]);
                float x2 = featexp(acc[f][2]), x3 = featexp(acc[f][3]);
                int c = nh * 32 + f * 8 + qk;
                gkp[tr * 32 + (c >> 1)] = pack2(x0, x1);
                gkp[(tr + 8) * 32 + (c >> 1)] = pack2(x2, x3);
                uint32_t hi, lo;
                packhl2(x0, x1, hi, lo);
                *(uint32_t*)(sm + P1_KPH + tr * RSB + c * 2) = hi;
                *(uint32_t*)(sm + P1_KPL + tr * RSB + c * 2) = lo;
                packhl2(x2, x3, hi, lo);
                *(uint32_t*)(sm + P1_KPH + (tr + 8) * RSB + c * 2) = hi;
                *(uint32_t*)(sm + P1_KPL + (tr + 8) * RSB + c * 2) = lo;
            }
        }

        // ---- Phase 4: LN(v) -> VT hi/lo ----
        {
            float xv[16];
#pragma unroll
            for (int i = 0; i < 4; i++) *(float4*)(xv + 4 * i) = *(const float4*)(vr + 4 * i);
            ln16(xv, GB, c0);
#pragma unroll
            for (int jj = 0; jj < 8; jj++) {
                uint32_t hi, lo;
                packhl2(xv[2 * jj], xv[2 * jj + 1], hi, lo);
                *(uint32_t*)(sm + P1_VTH + t * RSB + (c0 + 2 * jj) * 2) = hi;
                *(uint32_t*)(sm + P1_VTL + t * RSB + (c0 + 2 * jj) * 2) = lo;
            }
        }
        __syncthreads();   // S2

        // ---- Phase 5: GEMM2 3-term ----
#pragma unroll
        for (int ks = 0; ks < 4; ks++) {
            uint32_t Ah[4], Al[4];
            ldsm4t(Ah, aG2 + ks * 16 * RSB);
            ldsm4t(Al, aG2 + PL + ks * 16 * RSB);
#pragma unroll
            for (int f2 = 0; f2 < 2; f2++) {
                uint32_t Bh[4], Bl[4];
                ldsm4t(Bh, bG2 + f2 * 32 + ks * 16 * RSB);
                ldsm4t(Bl, bG2 + PL + f2 * 32 + ks * 16 * RSB);
                mma3(acc2[f2 * 2],     Ah, Al, Bh[0], Bh[1], Bl[0], Bl[1]);
                mma3(acc2[f2 * 2 + 1], Ah, Al, Bh[2], Bh[3], Bl[2], Bl[3]);
            }
        }
    }

    float* gp = g_part + (size_t)(bh * 16 + bx) * 4096;
#pragma unroll
    for (int f = 0; f < 4; f++) {
        int n = nh * 32 + f * 8 + qk;
        *(float2*)(gp + tr * 64 + n) = make_float2(acc2[f][0], acc2[f][1]);
        *(float2*)(gp + (tr + 8) * 64 + n) = make_float2(acc2[f][2], acc2[f][3]);
    }
}

// ---------------------------------------------------------------------------
extern "C" __global__ void __launch_bounds__(256) fa_reduce()
{
    const int tid = blockIdx.x * 256 + threadIdx.x;
    const int bh = tid >> 10, e4 = tid & 1023;
    const float4* p = (const float4*)(g_part + (size_t)bh * 16 * 4096) + e4;
    float4 s = make_float4(0.f, 0.f, 0.f, 0.f);
#pragma unroll
    for (int c = 0; c < 16; ++c) {
        float4 a = p[(size_t)c * 1024];
        s.x += a.x; s.y += a.y; s.z += a.z; s.w += a.w;
    }
    s.x *= 0.1f; s.y *= 0.1f; s.z *= 0.1f; s.w *= 0.1f;
    const int m = e4 >> 4, n0 = (e4 & 15) * 4;
    const int base = bh * 2304 + m * 36 + (n0 >> 1);
    uint32_t hi, lo;
    packhl2(s.x, s.y, hi, lo);
    g_kvh[base] = hi; g_kvl[base] = lo;
    packhl2(s.z, s.w, hi, lo);
    g_kvh[base + 1] = hi; g_kvl[base + 1] = lo;
}

// ---------------------------------------------------------------------------
// Pass 2: pairwise-decoupled. All cross-warp deps are within warp pairs
// (w, w^4) sharing mb = wid&3. LN rows are pair-local; all four per-tile
// barriers are named pair barriers (bar.sync mb+1, 64).
// ---------------------------------------------------------------------------
extern "C" __global__ void __launch_bounds__(256, 4) fa_pass2(
    const float* __restrict__ q, const float* __restrict__ gamma,
    const float* __restrict__ beta, float* __restrict__ out)
{
    extern __shared__ char sm[];
    const uint32_t sb = smem_u32(sm);
    float*  DEN = (float*)(sm + P2_DEN);
    float2* PD  = (float2*)(sm + P2_PD);
    float*  GB  = (float*)(sm + P2_GB);

    const int tid = threadIdx.x, lane = tid & 31, wid = tid >> 5;
    const int bh = blockIdx.y, bx = blockIdx.x;
    const int mb = wid & 3, nh = wid >> 2;
    // pair-local LN row assignment: pair mb covers rows mb*16..mb*16+15
    const int t = mb * 16 + nh * 8 + (lane >> 2);
    const int c0 = (lane & 3) * 16;

    if (tid < 64) GB[tid] = gamma[tid];
    else if (tid < 128) GB[tid] = beta[tid - 64];
    {
        const uint4* src = (const uint4*)g_pjh;
        uint4* dst = (uint4*)(sm + P2_PJ);
        for (int i = tid; i < 576; i += 256) dst[i] = src[i];
        const uint4* kh = (const uint4*)(g_kvh + bh * 2304);
        const uint4* kl = (const uint4*)(g_kvl + bh * 2304);
        uint4* dh = (uint4*)(sm + P2_KVH);
        uint4* dl = (uint4*)(sm + P2_KVL);
        for (int i = tid; i < 576; i += 256) { dh[i] = kh[i]; dl[i] = kl[i]; }
    }
    __syncthreads();   // prologue: PJ/KV/GB visible to all

    const int r = lane >> 2, qk = (lane & 3) * 2;
    const int tr = mb * 16 + r;
    const int l7 = lane & 7, l8 = (lane >> 3) & 1, l16 = (lane >> 4) & 1;

    const uint32_t aG3 = sb + P2_QNH + (mb * 16 + l7 + l8 * 8) * RSB + l16 * 16;
    const uint32_t bG3 = sb + P2_PJ + (nh * 32 + l7 + l16 * 8) * RSB + l8 * 16;
    const uint32_t bG4 = sb + P2_KVH + (l7 + l8 * 8) * RSB + (nh * 32 + l16 * 8) * 2;

#define PAIRBAR() asm volatile("bar.sync %0, 64;" :: "r"(mb + 1) : "memory")

    for (int it = 0; it < TPC; ++it) {
        const int t0 = (bx * TPC + it) * 64;
        float x[16];

        // ---- LN + L2 of q -> QN rows of this pair ----
        {
            const float* qr = q + ((size_t)(bh * TV + t0 + t)) * 64 + c0;
#pragma unroll
            for (int i = 0; i < 4; i++) *(float4*)(x + 4 * i) = *(const float4*)(qr + 4 * i);
            ln16(x, GB, c0);
            float n2 = 0.f;
#pragma unroll
            for (int j = 0; j < 16; j++) n2 += x[j] * x[j];
            n2 = qred(n2);
            float inv = 1.f / fmaxf(sqrtf(n2), 1e-12f);
#pragma unroll
            for (int jj = 0; jj < 8; jj++)
                *(uint32_t*)(sm + P2_QNH + t * RSB + (c0 + 2 * jj) * 2) =
                    pack2(x[2 * jj] * inv, x[2 * jj + 1] * inv);
        }
        PAIRBAR();   // B1: pair QN rows ready

        // ---- GEMM3 single-bf16: D3[t][m] = QN @ PJ^T ----
        float acc[4][4];
#pragma unroll
        for (int f = 0; f < 4; f++)
#pragma unroll
            for (int j = 0; j < 4; j++) acc[f][j] = 0.f;
#pragma unroll
        for (int ks = 0; ks < 4; ks++) {
            uint32_t Ah[4];
            ldsm4(Ah, aG3 + ks * 32);
#pragma unroll
            for (int f2 = 0; f2 < 2; f2++) {
                uint32_t Bh[4];
                ldsm4(Bh, bG3 + f2 * 16 * RSB + ks * 32);
                mma_bf16(acc[f2 * 2],     Ah, Bh[0], Bh[1]);
                mma_bf16(acc[f2 * 2 + 1], Ah, Bh[2], Bh[3]);
            }
        }
        PAIRBAR();   // B2: pair QN reads done (qp overlays same rows)

        // ---- qp = featexp(D3) -> planes; denom partials vs g_kp ----
        {
            const uint32_t* gkp = g_kp + ((size_t)bh * TV + t0) * 32;
            float den0 = 0.f, den1 = 0.f;
#pragma unroll
            for (int f = 0; f < 4; f++) {
                float x0 = featexp(acc[f][0]), x1 = featexp(acc[f][1]);
                float x2 = featexp(acc[f][2]), x3 = featexp(acc[f][3]);
                int c = nh * 32 + f * 8 + qk;
                uint32_t hi, lo;
                packhl2(x0, x1, hi, lo);
                *(uint32_t*)(sm + P2_QNH + tr * RSB + c * 2) = hi;
                *(uint32_t*)(sm + P2_QPL + tr * RSB + c * 2) = lo;
                packhl2(x2, x3, hi, lo);
                *(uint32_t*)(sm + P2_QNH + (tr + 8) * RSB + c * 2) = hi;
                *(uint32_t*)(sm + P2_QPL + (tr + 8) * RSB + c * 2) = lo;
                float2 k0 = unpk2(gkp[tr * 32 + (c >> 1)]);
                float2 k1 = unpk2(gkp[(tr + 8) * 32 + (c >> 1)]);
                den0 += x0 * k0.x + x1 * k0.y;
                den1 += x2 * k1.x + x3 * k1.y;
            }
            den0 = qred(den0);
            den1 = qred(den1);
            if ((lane & 3) == 0) { DEN[nh * 64 + tr] = den0; DEN[nh * 64 + tr + 8] = den1; }
        }
        PAIRBAR();   // B3: pair qp planes + DEN ready

        // ---- GEMM4 3-term: D4[t][n] = qp @ kv ----
        float acc2[4][4];
#pragma unroll
        for (int f = 0; f < 4; f++)
#pragma unroll
            for (int j = 0; j < 4; j++) acc2[f][j] = 0.f;
#pragma unroll
        for (int ks = 0; ks < 4; ks++) {
            uint32_t Ah[4], Al[4];
            ldsm4(Ah, aG3 + ks * 32);
            ldsm4(Al, aG3 + PL + ks * 32);
#pragma unroll
            for (int f2 = 0; f2 < 2; f2++) {
                uint32_t Bh[4], Bl[4];
                ldsm4t(Bh, bG4 + f2 * 32 + ks * 16 * RSB);
                ldsm4t(Bl, bG4 + PL + f2 * 32 + ks * 16 * RSB);
                mma3(acc2[f2 * 2],     Ah, Al, Bh[0], Bh[1], Bl[0], Bl[1]);
                mma3(acc2[f2 * 2 + 1], Ah, Al, Bh[2], Bh[3], Bl[2], Bl[3]);
            }
        }

        // ---- epilogue4: scale by 0.1/den; partial row stats -> PD ----
        {
            float s0 = 0.1f / fmaxf(DEN[tr] + DEN[64 + tr], DEN_EPS);
            float s1 = 0.1f / fmaxf(DEN[tr + 8] + DEN[64 + tr + 8], DEN_EPS);
            float sA = 0.f, ssA = 0.f, sB = 0.f, ssB = 0.f;
#pragma unroll
            for (int f = 0; f < 4; f++) {
                acc2[f][0] *= s0; acc2[f][1] *= s0;
                acc2[f][2] *= s1; acc2[f][3] *= s1;
                sA += acc2[f][0] + acc2[f][1];
                ssA += acc2[f][0] * acc2[f][0] + acc2[f][1] * acc2[f][1];
                sB += acc2[f][2] + acc2[f][3];
                ssB += acc2[f][2] * acc2[f][2] + acc2[f][3] * acc2[f][3];
            }
            sA = qred(sA); ssA = qred(ssA);
            sB = qred(sB); ssB = qred(ssB);
            if ((lane & 3) == 0) {
                PD[nh * 128 + tr] = make_float2(sA, ssA);
                PD[nh * 128 + tr + 8] = make_float2(sB, ssB);
            }
        }
        PAIRBAR();   // B4: pair PD ready; also orders GEMM4 reads vs next LNq

        // ---- final LN from registers; direct gmem store ----
        {
            float2 a0 = PD[tr],     b0 = PD[128 + tr];
            float2 a1 = PD[tr + 8], b1 = PD[128 + tr + 8];
            float muA = (a0.x + b0.x) * (1.f / 64.f);
            float rsdA = rsqrtf((a0.y + b0.y) * (1.f / 64.f) - muA * muA + LN_EPS);
            float muB = (a1.x + b1.x) * (1.f / 64.f);
            float rsdB = rsqrtf((a1.y + b1.y) * (1.f / 64.f) - muB * muB + LN_EPS);
            float* o0 = out + ((size_t)(bh * TV + t0 + tr)) * 64;
            float* o1 = out + ((size_t)(bh * TV + t0 + tr + 8)) * 64;
#pragma unroll
            for (int f = 0; f < 4; f++) {
                int c = nh * 32 + f * 8 + qk;
                float g0 = GB[c], g1 = GB[c + 1];
                float be0 = GB[64 + c], be1 = GB[64 + c + 1];
                *(float2*)(o0 + c) = make_float2((acc2[f][0] - muA) * rsdA * g0 + be0,
                                                 (acc2[f][1] - muA) * rsdA * g1 + be1);
                *(float2*)(o1 + c) = make_float2((acc2[f][2] - muB) * rsdB * g0 + be0,
                                                 (acc2[f][3] - muB) * rsdB * g1 + be1);
            }
        }
        // next LNq writes QN rows of this pair; ordered by B4 (GEMM4 reads done)
    }
#undef PAIRBAR
}

// ---------------------------------------------------------------------------
extern "C" void kernel_launch(void* const* d_in, const int* in_sizes, int n_in,
                              void* d_out, int out_size)
{
    const float* q     = (const float*)d_in[0];
    const float* k     = (const float*)d_in[1];
    const float* v     = (const float*)d_in[2];
    const float* proj  = (const float*)d_in[3];
    const float* gamma = (const float*)d_in[4];
    const float* beta  = (const float*)d_in[5];
    float* out = (float*)d_out;

    cudaFuncSetAttribute(fa_pass1, cudaFuncAttributeMaxDynamicSharedMemorySize, P1_BYTES);
    cudaFuncSetAttribute(fa_pass2, cudaFuncAttributeMaxDynamicSharedMemorySize, P2_BYTES);

    fa_setup<<<1, 256>>>(proj);
    fa_pass1<<<dim3(16, BHV), 256, P1_BYTES>>>(k, v, gamma, beta);
    fa_reduce<<<128, 256>>>();
    fa_pass2<<<dim3(16, BHV), 256, P2_BYTES>>>(q, gamma, beta, out);
}